// round 4
// baseline (speedup 1.0000x reference)
#include <cuda_runtime.h>
#include <math.h>

typedef unsigned long long ull;

#define NB   512
#define DM   128
#define DOUT 64
#define DP   32
#define NPIX 225
#define PSTR 228          // global per-channel pixel stride (floats)
#define PADP 292          // padded 17x17 (289) channel stride in smem
#define XST  256          // smem dense pixel stride
#define MAXF 31.75f
#define INV_MAXF (1.0f/31.75f)
#define MAXM (127.0f/3.515625f)

#define SMA (DM*PADP*4)               // k_dirconv smem
#define SMB (DM*XST*4)                // k_pw smem
#define SMC (DM*XST*4 + DOUT*PADP*4)  // k_fin smem

// ---------------- device scratch (no allocation) ----------------
__device__ __align__(16) float g_xs [4ull*NB*DM*PSTR];
__device__ __align__(16) float g_tmp[4ull*NB*DM*PSTR];
__device__ __align__(16) float g_wdc[12*DM*DM];   // dconv  [l*3+t][i][o]
__device__ __align__(16) float g_wc1[4*DM*DM];    // c1     [l][i][o]
__device__ __align__(16) float g_wr1[DM*DM];      // r0_w1  [i][o]
__device__ __align__(16) float g_wr2[DM*DM];      // r0_w2  [i][o]
__device__ __align__(16) float g_wfn[DM*DOUT];    // fin    [i][o]

// tap offsets (dr,dc): tap t reads x[h+dr][w+dc]
__constant__ int c_dr[4][3] = {{0,0,0},{-1,0,1},{-1,0,1},{1,0,-1}};
__constant__ int c_dc[4][3] = {{-1,0,1},{0,0,0},{-1,0,1},{-1,0,1}};

// ---------------- f32x2 helpers ----------------
__device__ __forceinline__ ull pack2(float lo, float hi) {
    ull r; asm("mov.b64 %0, {%1,%2};" : "=l"(r) : "f"(lo), "f"(hi)); return r;
}
__device__ __forceinline__ float2 unpack2(ull v) {
    float2 f; asm("mov.b64 {%0,%1}, %2;" : "=f"(f.x), "=f"(f.y) : "l"(v)); return f;
}
__device__ __forceinline__ ull fma2(ull a, ull b, ull c) {
    ull d; asm("fma.rn.f32x2 %0, %1, %2, %3;" : "=l"(d) : "l"(a), "l"(b), "l"(c)); return d;
}
__device__ __forceinline__ ull ldg2(const float* p) {
    ull v; asm("ld.global.nc.b64 %0, [%1];" : "=l"(v) : "l"(p)); return v;
}
__device__ __forceinline__ float silu(float x) {
    return __fdividef(x, 1.f + __expf(-x));
}

// ---------------- generic transpose: [m][R][C] -> [m][C][R] ----------------
__global__ void k_xpose(const float* __restrict__ src, float* __restrict__ dst,
                        int nmat, int R, int C) {
    int n = nmat * R * C;
    for (int idx = blockIdx.x * blockDim.x + threadIdx.x; idx < n;
         idx += gridDim.x * blockDim.x) {
        int m = idx / (R * C);
        int rem = idx - m * R * C;
        int r = rem / C, c = rem - r * C;
        dst[(m * C + c) * R + r] = src[idx];
    }
}

// ---------------- input map conv (2 -> 128) + silu ----------------
__global__ __launch_bounds__(256) void k_map(const float* __restrict__ x,
                                             const float* __restrict__ mw,
                                             const float* __restrict__ mb,
                                             float* __restrict__ xsb) {
    int b = blockIdx.x, d = blockIdx.y, tid = threadIdx.x;
    __shared__ float xp[2 * PADP];
    for (int i = tid; i < 2 * PADP; i += 256) xp[i] = 0.f;
    __syncthreads();
    const float* xb = x + (size_t)b * 2 * NPIX;
    for (int i = tid; i < 2 * NPIX; i += 256) {
        int c = i / NPIX, p = i - c * NPIX;
        int h = p / 15, w = p - h * 15;
        xp[c * PADP + (h + 1) * 17 + (w + 1)] = xb[i];
    }
    __syncthreads();
    int dr[3], dc[3];
#pragma unroll
    for (int t = 0; t < 3; t++) { dr[t] = c_dr[d][t]; dc[t] = c_dc[d][t]; }
    float* dst = xsb + (size_t)(d * NB + b) * DM * PSTR;
    for (int idx = tid; idx < DM * NPIX; idx += 256) {
        int o = idx / NPIX, p = idx - o * NPIX;
        int h = p / 15, w = p - h * 15;
        float acc = mb[o];
#pragma unroll
        for (int t = 0; t < 3; t++) {
            int off = (h + 1 + dr[t]) * 17 + (w + 1 + dc[t]);
            acc += mw[(t * DM + o) * 2 + 0] * xp[off]
                 + mw[(t * DM + o) * 2 + 1] * xp[PADP + off];
        }
        dst[o * PSTR + p] = silu(acc);
    }
}

// -------- directional 3-tap conv 128->128 + silu (src -> dst), o-pair f32x2 --------
__global__ __launch_bounds__(256, 1) void k_dirconv(const float* __restrict__ srcb,
                                                    float* __restrict__ dstb,
                                                    const float* __restrict__ wT, // [3][i][o]
                                                    const float* __restrict__ bias) {
    extern __shared__ float xpad[];  // DM*PADP
    int b = blockIdx.x, d = blockIdx.y;
    int tid = threadIdx.x, lane = tid & 31, wid = tid >> 5;
    const float* src = srcb + (size_t)(d * NB + b) * DM * PSTR;
    float*       dst = dstb + (size_t)(d * NB + b) * DM * PSTR;

    for (int i = tid; i < DM * PADP; i += 256) xpad[i] = 0.f;
    __syncthreads();
    for (int c = wid; c < DM; c += 8) {
        const float* s = src + c * PSTR;
        float* xq = xpad + c * PADP;
        for (int p = lane; p < NPIX; p += 32) {
            int h = p / 15, w = p - h * 15;
            xq[(h + 1) * 17 + (w + 1)] = s[p];
        }
    }
    __syncthreads();

    int offs[3][8];
#pragma unroll
    for (int k = 0; k < 8; k++) {
        int p = lane + 32 * k;
        int pv = (p < NPIX) ? p : 0;
        int h = pv / 15, w = pv - h * 15;
#pragma unroll
        for (int t = 0; t < 3; t++)
            offs[t][k] = (h + 1 + c_dr[d][t]) * 17 + (w + 1 + c_dc[d][t]);
    }

    for (int pass = 0; pass < 4; pass++) {
        int obase = pass * 32 + wid * 4;
        ull acc[2][8];
#pragma unroll
        for (int j = 0; j < 2; j++)
#pragma unroll
            for (int k = 0; k < 8; k++) acc[j][k] = 0ull;

        for (int i = 0; i < DM; i++) {
            const float* xr = xpad + i * PADP;
#pragma unroll
            for (int t = 0; t < 3; t++) {
                const float* wp = wT + (t * DM + i) * DM + obase;
                ull w0 = ldg2(wp);
                ull w1 = ldg2(wp + 2);
#pragma unroll
                for (int k = 0; k < 8; k++) {
                    float xv = xr[offs[t][k]];
                    ull xx = pack2(xv, xv);
                    acc[0][k] = fma2(xx, w0, acc[0][k]);
                    acc[1][k] = fma2(xx, w1, acc[1][k]);
                }
            }
        }
#pragma unroll
        for (int j = 0; j < 2; j++) {
            int o0 = obase + 2 * j;
            float b0 = bias[o0], b1 = bias[o0 + 1];
            float* d0 = dst + o0 * PSTR;
            float* d1 = d0 + PSTR;
#pragma unroll
            for (int k = 0; k < 8; k++) {
                int p = lane + 32 * k;
                if (p < NPIX) {
                    float2 v = unpack2(acc[j][k]);
                    d0[p] = silu(v.x + b0);
                    d1[p] = silu(v.y + b1);
                }
            }
        }
    }
}

// -------- pointwise 128->128 + silu; ADD=1: dst = dst + silu(pw(src)) --------
template <int ADD>
__global__ __launch_bounds__(256, 1) void k_pw(const float* __restrict__ srcb,
                                               const float* __restrict__ wT,  // [i][o]
                                               const float* __restrict__ bias,
                                               float* __restrict__ dstb) {
    extern __shared__ float xsm[];  // DM*XST
    int b = blockIdx.x, d = blockIdx.y;
    int tid = threadIdx.x, lane = tid & 31, wid = tid >> 5;
    const float* src = srcb + (size_t)(d * NB + b) * DM * PSTR;
    float*       dst = dstb + (size_t)(d * NB + b) * DM * PSTR;

    for (int c = wid; c < DM; c += 8) {
        const float* s = src + c * PSTR;
        float* xq = xsm + c * XST;
        for (int p = lane; p < NPIX; p += 32) xq[p] = s[p];
        if (lane < 31) xq[NPIX + lane] = 0.f;
    }
    __syncthreads();

    for (int pass = 0; pass < 4; pass++) {
        int obase = pass * 32 + wid * 4;
        ull acc[4][4];
#pragma unroll
        for (int j = 0; j < 4; j++)
#pragma unroll
            for (int k = 0; k < 4; k++) acc[j][k] = 0ull;

        for (int i = 0; i < DM; i++) {
            float4 wv = *(const float4*)(wT + i * DM + obase);
            ull w0 = pack2(wv.x, wv.x), w1 = pack2(wv.y, wv.y);
            ull w2 = pack2(wv.z, wv.z), w3 = pack2(wv.w, wv.w);
            const ull* xr = (const ull*)(xsm + i * XST) + lane;
#pragma unroll
            for (int k = 0; k < 4; k++) {
                ull xx = xr[32 * k];
                acc[0][k] = fma2(xx, w0, acc[0][k]);
                acc[1][k] = fma2(xx, w1, acc[1][k]);
                acc[2][k] = fma2(xx, w2, acc[2][k]);
                acc[3][k] = fma2(xx, w3, acc[3][k]);
            }
        }
#pragma unroll
        for (int j = 0; j < 4; j++) {
            int o = obase + j;
            float bv = bias[o];
            float* dp = dst + o * PSTR;
#pragma unroll
            for (int k = 0; k < 4; k++) {
                int px = 2 * (lane + 32 * k);
                float2 v = unpack2(acc[j][k]);
                float y0 = silu(v.x + bv), y1 = silu(v.y + bv);
                if (px < NPIX)     dp[px]     = ADD ? dp[px]     + y0 : y0;
                if (px + 1 < NPIX) dp[px + 1] = ADD ? dp[px + 1] + y1 : y1;
            }
        }
    }
}

// -------- fused: fin(128->64) per dir, tanh-clamp, sum dirs, prelu/4, heads --------
__global__ __launch_bounds__(256, 1) void k_fin(
    const float* __restrict__ xsb, const float* __restrict__ wT,  // [i][o] 128x64
    const float* __restrict__ bias, const float* __restrict__ prelu,
    const float* __restrict__ pdww, const float* __restrict__ pdwb,
    const float* __restrict__ ppw,
    const float* __restrict__ vl1w, const float* __restrict__ vl1b,
    const float* __restrict__ vl2w, const float* __restrict__ vl2b,
    const float* __restrict__ vlfw, const float* __restrict__ vlfb,
    const float* __restrict__ pscale, const float* __restrict__ vscale,
    float* __restrict__ out) {
    extern __shared__ float sm[];
    float* xsm  = sm;              // DM*XST
    float* facc = sm + DM * XST;   // DOUT*PADP (padded 17x17 per channel)
    __shared__ float vbuf[32], h1[32], h2[32];
    int b = blockIdx.x, tid = threadIdx.x, lane = tid & 31, wid = tid >> 5;

    for (int i = tid; i < DOUT * PADP; i += 256) facc[i] = 0.f;

    for (int d = 0; d < 4; d++) {
        __syncthreads();
        const float* src = xsb + (size_t)(d * NB + b) * DM * PSTR;
        for (int c = wid; c < DM; c += 8) {
            const float* s = src + c * PSTR;
            float* xq = xsm + c * XST;
            for (int p = lane; p < NPIX; p += 32) xq[p] = s[p];
            if (lane < 31) xq[NPIX + lane] = 0.f;
        }
        __syncthreads();

        for (int pass = 0; pass < 2; pass++) {
            int obase = pass * 32 + wid * 4;
            ull acc[4][4];
#pragma unroll
            for (int j = 0; j < 4; j++)
#pragma unroll
                for (int k = 0; k < 4; k++) acc[j][k] = 0ull;

            for (int i = 0; i < DM; i++) {
                float4 wv = *(const float4*)(wT + i * DOUT + obase);
                ull w0 = pack2(wv.x, wv.x), w1 = pack2(wv.y, wv.y);
                ull w2 = pack2(wv.z, wv.z), w3 = pack2(wv.w, wv.w);
                const ull* xr = (const ull*)(xsm + i * XST) + lane;
#pragma unroll
                for (int k = 0; k < 4; k++) {
                    ull xx = xr[32 * k];
                    acc[0][k] = fma2(xx, w0, acc[0][k]);
                    acc[1][k] = fma2(xx, w1, acc[1][k]);
                    acc[2][k] = fma2(xx, w2, acc[2][k]);
                    acc[3][k] = fma2(xx, w3, acc[3][k]);
                }
            }
#pragma unroll
            for (int j = 0; j < 4; j++) {
                int o = obase + j;
                float bv = bias[o];
                float* fo = facc + o * PADP;
#pragma unroll
                for (int k = 0; k < 4; k++) {
                    int px = 2 * (lane + 32 * k);
                    float2 v = unpack2(acc[j][k]);
                    if (px < NPIX) {
                        int h = px / 15, w = px - h * 15;
                        fo[(h + 1) * 17 + w + 1] += MAXF * tanhf((v.x + bv) * INV_MAXF);
                    }
                    if (px + 1 < NPIX) {
                        int h = (px + 1) / 15, w = (px + 1) - h * 15;
                        fo[(h + 1) * 17 + w + 1] += MAXF * tanhf((v.y + bv) * INV_MAXF);
                    }
                }
            }
        }
    }
    __syncthreads();

    // prelu + /4 (in place, interior only; halo stays 0)
    for (int idx = tid; idx < DOUT * NPIX; idx += 256) {
        int o = idx / NPIX, p = idx - o * NPIX;
        int h = p / 15, w = p - h * 15;
        float* fp = &facc[o * PADP + (h + 1) * 17 + w + 1];
        float v = *fp;
        *fp = (v >= 0.f ? v : prelu[o] * v) * 0.25f;
    }
    __syncthreads();

    // policy head
    if (tid < NPIX) {
        int h = tid / 15, w = tid - h * 15;
        int base = (h + 1) * 17 + (w + 1);
        float acc = 0.f;
        for (int c = 0; c < DP; c++) {
            const float* fc = facc + c * PADP + base;
            const float* wk = pdww + c * 9;
            float s = pdwb[c];
#pragma unroll
            for (int r = 0; r < 3; r++)
#pragma unroll
                for (int cc = 0; cc < 3; cc++)
                    s += wk[r * 3 + cc] * fc[(r - 1) * 17 + (cc - 1)];
            s = (s >= 0.f) ? s : s * 0.0625f;
            s = fminf(fmaxf(s, -MAXF), MAXF);
            acc += ppw[c] * s;
        }
        acc = (acc >= 0.f) ? acc : acc * 0.0625f;
        out[NB * 3 + (size_t)b * NPIX + tid] = acc * pscale[0];
    }
    __syncthreads();

    // value head (warp 0)
    if (wid == 0) {
        const float* fc = facc + (DP + lane) * PADP;
        float s = 0.f;
        for (int h = 0; h < 15; h++)
#pragma unroll
            for (int w = 0; w < 15; w++) s += fc[(h + 1) * 17 + w + 1];
        vbuf[lane] = fmaxf(s * (1.f / 225.f), 0.f);
        __syncwarp();
        float a = vl1b[lane];
        for (int i = 0; i < 32; i++) a += vl1w[lane * 32 + i] * vbuf[i];
        h1[lane] = fminf(fmaxf(a, 0.f), MAXM);
        __syncwarp();
        float g = vl2b[lane];
        for (int i = 0; i < 32; i++) g += vl2w[lane * 32 + i] * h1[i];
        h2[lane] = fminf(fmaxf(g, 0.f), MAXM);
        __syncwarp();
        if (lane < 3) {
            float o = vlfb[lane];
            for (int i = 0; i < 32; i++) o += vlfw[lane * 32 + i] * h2[i];
            out[(size_t)b * 3 + lane] = o * vscale[0];
        }
    }
}

// ---------------- host ----------------
extern "C" void kernel_launch(void* const* d_in, const int* in_sizes, int n_in,
                              void* d_out, int out_size) {
    const float* x       = (const float*)d_in[0];
    const float* map_w   = (const float*)d_in[1];
    const float* map_b   = (const float*)d_in[2];
    const float* dconv_w = (const float*)d_in[3];
    const float* dconv_b = (const float*)d_in[4];
    const float* c1_w    = (const float*)d_in[5];
    const float* c1_b    = (const float*)d_in[6];
    const float* r0_w1   = (const float*)d_in[7];
    const float* r0_b1   = (const float*)d_in[8];
    const float* r0_w2   = (const float*)d_in[9];
    const float* r0_b2   = (const float*)d_in[10];
    const float* fin_w   = (const float*)d_in[11];
    const float* fin_b   = (const float*)d_in[12];
    const float* prelu_w = (const float*)d_in[13];
    const float* pdw_w   = (const float*)d_in[14];
    const float* pdw_b   = (const float*)d_in[15];
    const float* ppw_w   = (const float*)d_in[16];
    const float* vl1_w   = (const float*)d_in[17];
    const float* vl1_b   = (const float*)d_in[18];
    const float* vl2_w   = (const float*)d_in[19];
    const float* vl2_b   = (const float*)d_in[20];
    const float* vlf_w   = (const float*)d_in[21];
    const float* vlf_b   = (const float*)d_in[22];
    const float* pscale  = (const float*)d_in[23];
    const float* vscale  = (const float*)d_in[24];
    float* out = (float*)d_out;

    float *xs, *tmp, *wdc, *wc1, *wr1, *wr2, *wfn;
    cudaGetSymbolAddress((void**)&xs,  g_xs);
    cudaGetSymbolAddress((void**)&tmp, g_tmp);
    cudaGetSymbolAddress((void**)&wdc, g_wdc);
    cudaGetSymbolAddress((void**)&wc1, g_wc1);
    cudaGetSymbolAddress((void**)&wr1, g_wr1);
    cudaGetSymbolAddress((void**)&wr2, g_wr2);
    cudaGetSymbolAddress((void**)&wfn, g_wfn);

    cudaFuncSetAttribute(k_dirconv, cudaFuncAttributeMaxDynamicSharedMemorySize, SMA);
    cudaFuncSetAttribute(k_pw<0>,   cudaFuncAttributeMaxDynamicSharedMemorySize, SMB);
    cudaFuncSetAttribute(k_pw<1>,   cudaFuncAttributeMaxDynamicSharedMemorySize, SMB);
    cudaFuncSetAttribute(k_fin,     cudaFuncAttributeMaxDynamicSharedMemorySize, SMC);

    k_xpose<<<256, 256>>>(dconv_w, wdc, 12, DM, DM);
    k_xpose<<<256, 256>>>(c1_w,    wc1,  4, DM, DM);
    k_xpose<<<64,  256>>>(r0_w1,   wr1,  1, DM, DM);
    k_xpose<<<64,  256>>>(r0_w2,   wr2,  1, DM, DM);
    k_xpose<<<32,  256>>>(fin_w,   wfn,  1, DOUT, DM);

    dim3 gbd(NB, 4);
    k_map<<<gbd, 256>>>(x, map_w, map_b, xs);
    for (int l = 0; l < 4; l++) {
        k_dirconv<<<gbd, 256, SMA>>>(xs, tmp, wdc + l * 3 * DM * DM, dconv_b + l * DM);
        k_pw<1><<<gbd, 256, SMB>>>(tmp, wc1 + l * DM * DM, c1_b + l * DM, xs);
    }
    k_pw<0><<<gbd, 256, SMB>>>(xs, wr1, r0_b1, tmp);
    k_pw<1><<<gbd, 256, SMB>>>(tmp, wr2, r0_b2, xs);

    k_fin<<<NB, 256, SMC>>>(xs, wfn, fin_b, prelu_w, pdw_w, pdw_b, ppw_w,
                            vl1_w, vl1_b, vl2_w, vl2_b, vlf_w, vlf_b,
                            pscale, vscale, out);
}

// round 5
// speedup vs baseline: 1.1716x; 1.1716x over previous
#include <cuda_runtime.h>
#include <math.h>

typedef unsigned long long ull;

#define NB   512
#define DM   128
#define DOUT 64
#define DP   32
#define NPIX 225
#define PSTR 228          // global per-channel pixel stride (floats)
#define PADP 292          // padded 17x17 (289) channel stride in smem
#define XST  256          // smem dense pixel stride
#define MAXF 31.75f
#define INV_MAXF (1.0f/31.75f)
#define MAXM (127.0f/3.515625f)

#define SMA (DM*PADP*4)               // k_dirconv smem
#define SMB (DM*XST*4)                // k_pw smem
#define SMC (DM*XST*4 + DOUT*PADP*4)  // k_fin smem

// ---------------- device scratch (no allocation) ----------------
__device__ __align__(16) float g_xs [4ull*NB*DM*PSTR];
__device__ __align__(16) float g_tmp[4ull*NB*DM*PSTR];
__device__ __align__(16) float g_wdc[12*DM*DM];   // dconv  [l*3+t][i][o]
__device__ __align__(16) float g_wc1[4*DM*DM];    // c1     [l][i][o]
__device__ __align__(16) float g_wr1[DM*DM];      // r0_w1  [i][o]
__device__ __align__(16) float g_wr2[DM*DM];      // r0_w2  [i][o]
__device__ __align__(16) float g_wfn[DM*DOUT];    // fin    [i][o]

// tap offsets (dr,dc): tap t reads x[h+dr][w+dc]
__constant__ int c_dr[4][3] = {{0,0,0},{-1,0,1},{-1,0,1},{1,0,-1}};
__constant__ int c_dc[4][3] = {{-1,0,1},{0,0,0},{-1,0,1},{-1,0,1}};

// ---------------- f32x2 helpers ----------------
__device__ __forceinline__ ull pack2(float lo, float hi) {
    ull r; asm("mov.b64 %0, {%1,%2};" : "=l"(r) : "f"(lo), "f"(hi)); return r;
}
__device__ __forceinline__ float2 unpack2(ull v) {
    float2 f; asm("mov.b64 {%0,%1}, %2;" : "=f"(f.x), "=f"(f.y) : "l"(v)); return f;
}
__device__ __forceinline__ ull fma2(ull a, ull b, ull c) {
    ull d; asm("fma.rn.f32x2 %0, %1, %2, %3;" : "=l"(d) : "l"(a), "l"(b), "l"(c)); return d;
}
__device__ __forceinline__ ull ldg2(const float* p) {
    ull v; asm("ld.global.nc.b64 %0, [%1];" : "=l"(v) : "l"(p)); return v;
}
__device__ __forceinline__ float silu(float x) {
    return __fdividef(x, 1.f + __expf(-x));
}

// ---------------- transpose: dconv [12][o][i] -> [12][i][o] ----------------
__global__ void k_xpose(const float* __restrict__ src, float* __restrict__ dst,
                        int nmat, int R, int C) {
    int n = nmat * R * C;
    for (int idx = blockIdx.x * blockDim.x + threadIdx.x; idx < n;
         idx += gridDim.x * blockDim.x) {
        int m = idx / (R * C);
        int rem = idx - m * R * C;
        int r = rem / C, c = rem - r * C;
        dst[(m * C + c) * R + r] = src[idx];
    }
}

// ---------------- transpose the remaining 4 weight families in ONE launch ----------------
__global__ void k_xpose_rest(const float* __restrict__ c1,
                             const float* __restrict__ r1,
                             const float* __restrict__ r2,
                             const float* __restrict__ fin,
                             float* __restrict__ wc1, float* __restrict__ wr1,
                             float* __restrict__ wr2, float* __restrict__ wfn) {
    const int N1 = 4 * DM * DM;          // 65536
    const int N2 = N1 + DM * DM;         // 81920
    const int N3 = N2 + DM * DM;         // 98304
    const int N4 = N3 + DOUT * DM;       // 106496
    for (int idx = blockIdx.x * blockDim.x + threadIdx.x; idx < N4;
         idx += gridDim.x * blockDim.x) {
        if (idx < N1) {
            int m = idx / (DM * DM);
            int rem = idx - m * DM * DM;
            int r = rem / DM, c = rem - r * DM;
            wc1[(m * DM + c) * DM + r] = c1[idx];
        } else if (idx < N2) {
            int i2 = idx - N1;
            int r = i2 / DM, c = i2 - r * DM;
            wr1[c * DM + r] = r1[i2];
        } else if (idx < N3) {
            int i2 = idx - N2;
            int r = i2 / DM, c = i2 - r * DM;
            wr2[c * DM + r] = r2[i2];
        } else {
            int i2 = idx - N3;
            int r = i2 / DM, c = i2 - r * DM;  // r = o (64), c = i (128)
            wfn[c * DOUT + r] = fin[i2];
        }
    }
}

// ---------------- input map conv (2 -> 128) + silu ----------------
__global__ __launch_bounds__(256) void k_map(const float* __restrict__ x,
                                             const float* __restrict__ mw,
                                             const float* __restrict__ mb,
                                             float* __restrict__ xsb) {
    int b = blockIdx.x, d = blockIdx.y, tid = threadIdx.x;
    __shared__ float xp[2 * PADP];
    for (int i = tid; i < 2 * PADP; i += 256) xp[i] = 0.f;
    __syncthreads();
    const float* xb = x + (size_t)b * 2 * NPIX;
    for (int i = tid; i < 2 * NPIX; i += 256) {
        int c = i / NPIX, p = i - c * NPIX;
        int h = p / 15, w = p - h * 15;
        xp[c * PADP + (h + 1) * 17 + (w + 1)] = xb[i];
    }
    __syncthreads();
    int dr[3], dc[3];
#pragma unroll
    for (int t = 0; t < 3; t++) { dr[t] = c_dr[d][t]; dc[t] = c_dc[d][t]; }
    float* dst = xsb + (size_t)(d * NB + b) * DM * PSTR;
    for (int idx = tid; idx < DM * NPIX; idx += 256) {
        int o = idx / NPIX, p = idx - o * NPIX;
        int h = p / 15, w = p - h * 15;
        float acc = mb[o];
#pragma unroll
        for (int t = 0; t < 3; t++) {
            int off = (h + 1 + dr[t]) * 17 + (w + 1 + dc[t]);
            acc += mw[(t * DM + o) * 2 + 0] * xp[off]
                 + mw[(t * DM + o) * 2 + 1] * xp[PADP + off];
        }
        dst[o * PSTR + p] = silu(acc);
    }
}

// -------- directional 3-tap conv 128->128 + silu (src -> dst), o-pair f32x2 --------
// 512 threads: 16 warps, each warp owns 4 out-channels per pass, 2 passes.
__global__ __launch_bounds__(512, 1) void k_dirconv(const float* __restrict__ srcb,
                                                    float* __restrict__ dstb,
                                                    const float* __restrict__ wT, // [3][i][o]
                                                    const float* __restrict__ bias) {
    extern __shared__ float xpad[];  // DM*PADP
    int b = blockIdx.x, d = blockIdx.y;
    int tid = threadIdx.x, lane = tid & 31, wid = tid >> 5;
    const float* src = srcb + (size_t)(d * NB + b) * DM * PSTR;
    float*       dst = dstb + (size_t)(d * NB + b) * DM * PSTR;

    for (int i = tid; i < DM * PADP; i += 512) xpad[i] = 0.f;
    __syncthreads();
    for (int c = wid; c < DM; c += 16) {
        const float* s = src + c * PSTR;
        float* xq = xpad + c * PADP;
        for (int p = lane; p < NPIX; p += 32) {
            int h = p / 15, w = p - h * 15;
            xq[(h + 1) * 17 + (w + 1)] = s[p];
        }
    }
    __syncthreads();

    int offs[3][8];
#pragma unroll
    for (int k = 0; k < 8; k++) {
        int p = lane + 32 * k;
        int pv = (p < NPIX) ? p : 0;
        int h = pv / 15, w = pv - h * 15;
#pragma unroll
        for (int t = 0; t < 3; t++)
            offs[t][k] = (h + 1 + c_dr[d][t]) * 17 + (w + 1 + c_dc[d][t]);
    }

#pragma unroll
    for (int pass = 0; pass < 2; pass++) {
        int obase = pass * 64 + wid * 4;
        ull acc[2][8];
#pragma unroll
        for (int j = 0; j < 2; j++)
#pragma unroll
            for (int k = 0; k < 8; k++) acc[j][k] = 0ull;

#pragma unroll 2
        for (int i = 0; i < DM; i++) {
            const float* xr = xpad + i * PADP;
#pragma unroll
            for (int t = 0; t < 3; t++) {
                const float* wp = wT + (t * DM + i) * DM + obase;
                ull w0 = ldg2(wp);
                ull w1 = ldg2(wp + 2);
#pragma unroll
                for (int k = 0; k < 8; k++) {
                    float xv = xr[offs[t][k]];
                    ull xx = pack2(xv, xv);
                    acc[0][k] = fma2(xx, w0, acc[0][k]);
                    acc[1][k] = fma2(xx, w1, acc[1][k]);
                }
            }
        }
#pragma unroll
        for (int j = 0; j < 2; j++) {
            int o0 = obase + 2 * j;
            float b0 = bias[o0], b1 = bias[o0 + 1];
            float* d0 = dst + o0 * PSTR;
            float* d1 = d0 + PSTR;
#pragma unroll
            for (int k = 0; k < 8; k++) {
                int p = lane + 32 * k;
                if (p < NPIX) {
                    float2 v = unpack2(acc[j][k]);
                    d0[p] = silu(v.x + b0);
                    d1[p] = silu(v.y + b1);
                }
            }
        }
    }
}

// -------- pointwise 128->128 + silu; ADD=1: dst = dst + silu(pw(src)) --------
// 512 threads: 16 warps x 4 o-channels, 2 passes. Pixel-pair f32x2 (no x packs).
template <int ADD>
__global__ __launch_bounds__(512, 1) void k_pw(const float* __restrict__ srcb,
                                               const float* __restrict__ wT,  // [i][o]
                                               const float* __restrict__ bias,
                                               float* __restrict__ dstb) {
    extern __shared__ float xsm[];  // DM*XST
    int b = blockIdx.x, d = blockIdx.y;
    int tid = threadIdx.x, lane = tid & 31, wid = tid >> 5;
    const float* src = srcb + (size_t)(d * NB + b) * DM * PSTR;
    float*       dst = dstb + (size_t)(d * NB + b) * DM * PSTR;

    for (int c = wid; c < DM; c += 16) {
        const float* s = src + c * PSTR;
        float* xq = xsm + c * XST;
        for (int p = lane; p < NPIX; p += 32) xq[p] = s[p];
        if (lane < 31) xq[NPIX + lane] = 0.f;
    }
    __syncthreads();

#pragma unroll
    for (int pass = 0; pass < 2; pass++) {
        int obase = pass * 64 + wid * 4;
        ull acc[4][4];
#pragma unroll
        for (int j = 0; j < 4; j++)
#pragma unroll
            for (int k = 0; k < 4; k++) acc[j][k] = 0ull;

#pragma unroll 4
        for (int i = 0; i < DM; i++) {
            float4 wv = *(const float4*)(wT + i * DM + obase);
            ull w0 = pack2(wv.x, wv.x), w1 = pack2(wv.y, wv.y);
            ull w2 = pack2(wv.z, wv.z), w3 = pack2(wv.w, wv.w);
            const ull* xr = (const ull*)(xsm + i * XST) + lane;
#pragma unroll
            for (int k = 0; k < 4; k++) {
                ull xx = xr[32 * k];
                acc[0][k] = fma2(xx, w0, acc[0][k]);
                acc[1][k] = fma2(xx, w1, acc[1][k]);
                acc[2][k] = fma2(xx, w2, acc[2][k]);
                acc[3][k] = fma2(xx, w3, acc[3][k]);
            }
        }
#pragma unroll
        for (int j = 0; j < 4; j++) {
            int o = obase + j;
            float bv = bias[o];
            float* dp = dst + o * PSTR;
#pragma unroll
            for (int k = 0; k < 4; k++) {
                int px = 2 * (lane + 32 * k);
                float2 v = unpack2(acc[j][k]);
                float y0 = silu(v.x + bv), y1 = silu(v.y + bv);
                if (px < NPIX)     dp[px]     = ADD ? dp[px]     + y0 : y0;
                if (px + 1 < NPIX) dp[px + 1] = ADD ? dp[px + 1] + y1 : y1;
            }
        }
    }
}

// -------- fused: fin(128->64) per dir, tanh-clamp, sum dirs, prelu/4, heads --------
__global__ __launch_bounds__(256, 1) void k_fin(
    const float* __restrict__ xsb, const float* __restrict__ wT,  // [i][o] 128x64
    const float* __restrict__ bias, const float* __restrict__ prelu,
    const float* __restrict__ pdww, const float* __restrict__ pdwb,
    const float* __restrict__ ppw,
    const float* __restrict__ vl1w, const float* __restrict__ vl1b,
    const float* __restrict__ vl2w, const float* __restrict__ vl2b,
    const float* __restrict__ vlfw, const float* __restrict__ vlfb,
    const float* __restrict__ pscale, const float* __restrict__ vscale,
    float* __restrict__ out) {
    extern __shared__ float sm[];
    float* xsm  = sm;              // DM*XST
    float* facc = sm + DM * XST;   // DOUT*PADP (padded 17x17 per channel)
    __shared__ float vbuf[32], h1[32], h2[32];
    int b = blockIdx.x, tid = threadIdx.x, lane = tid & 31, wid = tid >> 5;

    for (int i = tid; i < DOUT * PADP; i += 256) facc[i] = 0.f;

    for (int d = 0; d < 4; d++) {
        __syncthreads();
        const float* src = xsb + (size_t)(d * NB + b) * DM * PSTR;
        for (int c = wid; c < DM; c += 8) {
            const float* s = src + c * PSTR;
            float* xq = xsm + c * XST;
            for (int p = lane; p < NPIX; p += 32) xq[p] = s[p];
            if (lane < 31) xq[NPIX + lane] = 0.f;
        }
        __syncthreads();

        for (int pass = 0; pass < 2; pass++) {
            int obase = pass * 32 + wid * 4;
            ull acc[4][4];
#pragma unroll
            for (int j = 0; j < 4; j++)
#pragma unroll
                for (int k = 0; k < 4; k++) acc[j][k] = 0ull;

#pragma unroll 4
            for (int i = 0; i < DM; i++) {
                float4 wv = *(const float4*)(wT + i * DOUT + obase);
                ull w0 = pack2(wv.x, wv.x), w1 = pack2(wv.y, wv.y);
                ull w2 = pack2(wv.z, wv.z), w3 = pack2(wv.w, wv.w);
                const ull* xr = (const ull*)(xsm + i * XST) + lane;
#pragma unroll
                for (int k = 0; k < 4; k++) {
                    ull xx = xr[32 * k];
                    acc[0][k] = fma2(xx, w0, acc[0][k]);
                    acc[1][k] = fma2(xx, w1, acc[1][k]);
                    acc[2][k] = fma2(xx, w2, acc[2][k]);
                    acc[3][k] = fma2(xx, w3, acc[3][k]);
                }
            }
#pragma unroll
            for (int j = 0; j < 4; j++) {
                int o = obase + j;
                float bv = bias[o];
                float* fo = facc + o * PADP;
#pragma unroll
                for (int k = 0; k < 4; k++) {
                    int px = 2 * (lane + 32 * k);
                    float2 v = unpack2(acc[j][k]);
                    if (px < NPIX) {
                        int h = px / 15, w = px - h * 15;
                        fo[(h + 1) * 17 + w + 1] += MAXF * tanhf((v.x + bv) * INV_MAXF);
                    }
                    if (px + 1 < NPIX) {
                        int h = (px + 1) / 15, w = (px + 1) - h * 15;
                        fo[(h + 1) * 17 + w + 1] += MAXF * tanhf((v.y + bv) * INV_MAXF);
                    }
                }
            }
        }
    }
    __syncthreads();

    // prelu + /4 (in place, interior only; halo stays 0)
    for (int idx = tid; idx < DOUT * NPIX; idx += 256) {
        int o = idx / NPIX, p = idx - o * NPIX;
        int h = p / 15, w = p - h * 15;
        float* fp = &facc[o * PADP + (h + 1) * 17 + w + 1];
        float v = *fp;
        *fp = (v >= 0.f ? v : prelu[o] * v) * 0.25f;
    }
    __syncthreads();

    // policy head
    if (tid < NPIX) {
        int h = tid / 15, w = tid - h * 15;
        int base = (h + 1) * 17 + (w + 1);
        float acc = 0.f;
        for (int c = 0; c < DP; c++) {
            const float* fc = facc + c * PADP + base;
            const float* wk = pdww + c * 9;
            float s = pdwb[c];
#pragma unroll
            for (int r = 0; r < 3; r++)
#pragma unroll
                for (int cc = 0; cc < 3; cc++)
                    s += wk[r * 3 + cc] * fc[(r - 1) * 17 + (cc - 1)];
            s = (s >= 0.f) ? s : s * 0.0625f;
            s = fminf(fmaxf(s, -MAXF), MAXF);
            acc += ppw[c] * s;
        }
        acc = (acc >= 0.f) ? acc : acc * 0.0625f;
        out[NB * 3 + (size_t)b * NPIX + tid] = acc * pscale[0];
    }
    __syncthreads();

    // value head (warp 0)
    if (wid == 0) {
        const float* fc = facc + (DP + lane) * PADP;
        float s = 0.f;
        for (int h = 0; h < 15; h++)
#pragma unroll
            for (int w = 0; w < 15; w++) s += fc[(h + 1) * 17 + w + 1];
        vbuf[lane] = fmaxf(s * (1.f / 225.f), 0.f);
        __syncwarp();
        float a = vl1b[lane];
        for (int i = 0; i < 32; i++) a += vl1w[lane * 32 + i] * vbuf[i];
        h1[lane] = fminf(fmaxf(a, 0.f), MAXM);
        __syncwarp();
        float g = vl2b[lane];
        for (int i = 0; i < 32; i++) g += vl2w[lane * 32 + i] * h1[i];
        h2[lane] = fminf(fmaxf(g, 0.f), MAXM);
        __syncwarp();
        if (lane < 3) {
            float o = vlfb[lane];
            for (int i = 0; i < 32; i++) o += vlfw[lane * 32 + i] * h2[i];
            out[(size_t)b * 3 + lane] = o * vscale[0];
        }
    }
}

// ---------------- host ----------------
extern "C" void kernel_launch(void* const* d_in, const int* in_sizes, int n_in,
                              void* d_out, int out_size) {
    const float* x       = (const float*)d_in[0];
    const float* map_w   = (const float*)d_in[1];
    const float* map_b   = (const float*)d_in[2];
    const float* dconv_w = (const float*)d_in[3];
    const float* dconv_b = (const float*)d_in[4];
    const float* c1_w    = (const float*)d_in[5];
    const float* c1_b    = (const float*)d_in[6];
    const float* r0_w1   = (const float*)d_in[7];
    const float* r0_b1   = (const float*)d_in[8];
    const float* r0_w2   = (const float*)d_in[9];
    const float* r0_b2   = (const float*)d_in[10];
    const float* fin_w   = (const float*)d_in[11];
    const float* fin_b   = (const float*)d_in[12];
    const float* prelu_w = (const float*)d_in[13];
    const float* pdw_w   = (const float*)d_in[14];
    const float* pdw_b   = (const float*)d_in[15];
    const float* ppw_w   = (const float*)d_in[16];
    const float* vl1_w   = (const float*)d_in[17];
    const float* vl1_b   = (const float*)d_in[18];
    const float* vl2_w   = (const float*)d_in[19];
    const float* vl2_b   = (const float*)d_in[20];
    const float* vlf_w   = (const float*)d_in[21];
    const float* vlf_b   = (const float*)d_in[22];
    const float* pscale  = (const float*)d_in[23];
    const float* vscale  = (const float*)d_in[24];
    float* out = (float*)d_out;

    float *xs, *tmp, *wdc, *wc1, *wr1, *wr2, *wfn;
    cudaGetSymbolAddress((void**)&xs,  g_xs);
    cudaGetSymbolAddress((void**)&tmp, g_tmp);
    cudaGetSymbolAddress((void**)&wdc, g_wdc);
    cudaGetSymbolAddress((void**)&wc1, g_wc1);
    cudaGetSymbolAddress((void**)&wr1, g_wr1);
    cudaGetSymbolAddress((void**)&wr2, g_wr2);
    cudaGetSymbolAddress((void**)&wfn, g_wfn);

    cudaFuncSetAttribute(k_dirconv, cudaFuncAttributeMaxDynamicSharedMemorySize, SMA);
    cudaFuncSetAttribute(k_pw<0>,   cudaFuncAttributeMaxDynamicSharedMemorySize, SMB);
    cudaFuncSetAttribute(k_pw<1>,   cudaFuncAttributeMaxDynamicSharedMemorySize, SMB);
    cudaFuncSetAttribute(k_fin,     cudaFuncAttributeMaxDynamicSharedMemorySize, SMC);

    // launch 1 & 2: weight transposes (so ncu -s 5 -c 1 lands on k_dirconv layer 2)
    k_xpose<<<256, 256>>>(dconv_w, wdc, 12, DM, DM);
    k_xpose_rest<<<128, 256>>>(c1_w, r0_w1, r0_w2, fin_w, wc1, wr1, wr2, wfn);

    dim3 gbd(NB, 4);
    k_map<<<gbd, 256>>>(x, map_w, map_b, xs);                              // launch 3
    for (int l = 0; l < 4; l++) {
        k_dirconv<<<gbd, 512, SMA>>>(xs, tmp, wdc + l * 3 * DM * DM,       // 4,6,8,10
                                     dconv_b + l * DM);
        k_pw<1><<<gbd, 512, SMB>>>(tmp, wc1 + l * DM * DM, c1_b + l * DM, xs); // 5,7,9,11
    }
    k_pw<0><<<gbd, 512, SMB>>>(xs, wr1, r0_b1, tmp);
    k_pw<1><<<gbd, 512, SMB>>>(tmp, wr2, r0_b2, xs);

    k_fin<<<NB, 256, SMC>>>(xs, wfn, fin_b, prelu_w, pdw_w, pdw_b, ppw_w,
                            vl1_w, vl1_b, vl2_w, vl2_b, vlf_w, vlf_b,
                            pscale, vscale, out);
}

// round 6
// speedup vs baseline: 1.2531x; 1.0695x over previous
#include <cuda_runtime.h>
#include <math.h>

typedef unsigned long long ull;

#define NB   512
#define DM   128
#define DOUT 64
#define DP   32
#define NPIX 225
#define PSTR 228          // global per-channel pixel stride (floats)
#define PADP 292          // padded 17x17 (289) channel stride in smem
#define XST  256          // smem dense pixel stride
#define MAXF 31.75f
#define INV_MAXF (1.0f/31.75f)
#define MAXM (127.0f/3.515625f)

#define SMA (DM*PADP*4)               // k_dirconv smem
#define SMB (DM*XST*4)                // k_pw smem
#define SMC (DM*XST*4 + DOUT*PADP*4)  // k_fin smem

// ---------------- device scratch (no allocation) ----------------
__device__ __align__(16) float g_xs [4ull*NB*DM*PSTR];
__device__ __align__(16) float g_tmp[4ull*NB*DM*PSTR];
__device__ __align__(16) float g_wdc[12*DM*DM];   // dconv  [l*3+t][i][o]
__device__ __align__(16) float g_wc1[4*DM*DM];    // c1     [l][i][o]
__device__ __align__(16) float g_wr1[DM*DM];      // r0_w1  [i][o]
__device__ __align__(16) float g_wr2[DM*DM];      // r0_w2  [i][o]
__device__ __align__(16) float g_wfn[DM*DOUT];    // fin    [i][o]

// tap offsets (dr,dc): tap t reads x[h+dr][w+dc]
__constant__ int c_dr[4][3] = {{0,0,0},{-1,0,1},{-1,0,1},{1,0,-1}};
__constant__ int c_dc[4][3] = {{-1,0,1},{0,0,0},{-1,0,1},{-1,0,1}};

// ---------------- f32x2 helpers ----------------
__device__ __forceinline__ ull pack2(float lo, float hi) {
    ull r; asm("mov.b64 %0, {%1,%2};" : "=l"(r) : "f"(lo), "f"(hi)); return r;
}
__device__ __forceinline__ float2 unpack2(ull v) {
    float2 f; asm("mov.b64 {%0,%1}, %2;" : "=f"(f.x), "=f"(f.y) : "l"(v)); return f;
}
__device__ __forceinline__ ull fma2(ull a, ull b, ull c) {
    ull d; asm("fma.rn.f32x2 %0, %1, %2, %3;" : "=l"(d) : "l"(a), "l"(b), "l"(c)); return d;
}
// 16-byte weight load: two o-pairs
__device__ __forceinline__ void ldg2x2(const float* p, ull& a, ull& b) {
    asm("ld.global.nc.v2.u64 {%0,%1}, [%2];" : "=l"(a), "=l"(b) : "l"(p));
}
__device__ __forceinline__ float silu(float x) {
    return __fdividef(x, 1.f + __expf(-x));
}

// ---------------- transpose: dconv [12][o][i] -> [12][i][o] ----------------
__global__ void k_xpose(const float* __restrict__ src, float* __restrict__ dst,
                        int nmat, int R, int C) {
    int n = nmat * R * C;
    for (int idx = blockIdx.x * blockDim.x + threadIdx.x; idx < n;
         idx += gridDim.x * blockDim.x) {
        int m = idx / (R * C);
        int rem = idx - m * R * C;
        int r = rem / C, c = rem - r * C;
        dst[(m * C + c) * R + r] = src[idx];
    }
}

// ---------------- transpose the remaining 4 weight families in ONE launch ----------------
__global__ void k_xpose_rest(const float* __restrict__ c1,
                             const float* __restrict__ r1,
                             const float* __restrict__ r2,
                             const float* __restrict__ fin,
                             float* __restrict__ wc1, float* __restrict__ wr1,
                             float* __restrict__ wr2, float* __restrict__ wfn) {
    const int N1 = 4 * DM * DM;
    const int N2 = N1 + DM * DM;
    const int N3 = N2 + DM * DM;
    const int N4 = N3 + DOUT * DM;
    for (int idx = blockIdx.x * blockDim.x + threadIdx.x; idx < N4;
         idx += gridDim.x * blockDim.x) {
        if (idx < N1) {
            int m = idx / (DM * DM);
            int rem = idx - m * DM * DM;
            int r = rem / DM, c = rem - r * DM;
            wc1[(m * DM + c) * DM + r] = c1[idx];
        } else if (idx < N2) {
            int i2 = idx - N1;
            int r = i2 / DM, c = i2 - r * DM;
            wr1[c * DM + r] = r1[i2];
        } else if (idx < N3) {
            int i2 = idx - N2;
            int r = i2 / DM, c = i2 - r * DM;
            wr2[c * DM + r] = r2[i2];
        } else {
            int i2 = idx - N3;
            int r = i2 / DM, c = i2 - r * DM;  // r = o (64), c = i (128)
            wfn[c * DOUT + r] = fin[i2];
        }
    }
}

// ---------------- input map conv (2 -> 128) + silu ----------------
__global__ __launch_bounds__(256) void k_map(const float* __restrict__ x,
                                             const float* __restrict__ mw,
                                             const float* __restrict__ mb,
                                             float* __restrict__ xsb) {
    int b = blockIdx.x, d = blockIdx.y, tid = threadIdx.x;
    __shared__ float xp[2 * PADP];
    for (int i = tid; i < 2 * PADP; i += 256) xp[i] = 0.f;
    __syncthreads();
    const float* xb = x + (size_t)b * 2 * NPIX;
    for (int i = tid; i < 2 * NPIX; i += 256) {
        int c = i / NPIX, p = i - c * NPIX;
        int h = p / 15, w = p - h * 15;
        xp[c * PADP + (h + 1) * 17 + (w + 1)] = xb[i];
    }
    __syncthreads();
    int dr[3], dc[3];
#pragma unroll
    for (int t = 0; t < 3; t++) { dr[t] = c_dr[d][t]; dc[t] = c_dc[d][t]; }
    float* dst = xsb + (size_t)(d * NB + b) * DM * PSTR;
    for (int idx = tid; idx < DM * NPIX; idx += 256) {
        int o = idx / NPIX, p = idx - o * NPIX;
        int h = p / 15, w = p - h * 15;
        float acc = mb[o];
#pragma unroll
        for (int t = 0; t < 3; t++) {
            int off = (h + 1 + dr[t]) * 17 + (w + 1 + dc[t]);
            acc += mw[(t * DM + o) * 2 + 0] * xp[off]
                 + mw[(t * DM + o) * 2 + 1] * xp[PADP + off];
        }
        dst[o * PSTR + p] = silu(acc);
    }
}

// -------- directional 3-tap conv 128->128 + silu --------
// 512 threads / 16 warps. Each warp owns 8 output channels (4 o-pairs);
// 2 pixel groups of 128 pixels (lane + 32k, k=0..3).
// Per (i,t) per warp: 2x LDG.v2.b64 (weights) + 4 LDS + 4 pack + 16 FMA2.
__global__ __launch_bounds__(512, 1) void k_dirconv(const float* __restrict__ srcb,
                                                    float* __restrict__ dstb,
                                                    const float* __restrict__ wT, // [3][i][o]
                                                    const float* __restrict__ bias) {
    extern __shared__ float xpad[];  // DM*PADP
    int b = blockIdx.x, d = blockIdx.y;
    int tid = threadIdx.x, lane = tid & 31, wid = tid >> 5;
    const float* src = srcb + (size_t)(d * NB + b) * DM * PSTR;
    float*       dst = dstb + (size_t)(d * NB + b) * DM * PSTR;

    for (int i = tid; i < DM * PADP; i += 512) xpad[i] = 0.f;
    __syncthreads();
    for (int c = wid; c < DM; c += 16) {
        const float* s = src + c * PSTR;
        float* xq = xpad + c * PADP;
        for (int p = lane; p < NPIX; p += 32) {
            int h = p / 15, w = p - h * 15;
            xq[(h + 1) * 17 + (w + 1)] = s[p];
        }
    }
    __syncthreads();

    const int obase = wid * 8;    // warp's 8 output channels

#pragma unroll
    for (int pg = 0; pg < 2; pg++) {
        int offs[3][4];
#pragma unroll
        for (int k = 0; k < 4; k++) {
            int p = pg * 128 + lane + 32 * k;
            int pv = (p < NPIX) ? p : 0;
            int h = pv / 15, w = pv - h * 15;
#pragma unroll
            for (int t = 0; t < 3; t++)
                offs[t][k] = (h + 1 + c_dr[d][t]) * 17 + (w + 1 + c_dc[d][t]);
        }

        ull acc[4][4];
#pragma unroll
        for (int j = 0; j < 4; j++)
#pragma unroll
            for (int k = 0; k < 4; k++) acc[j][k] = 0ull;

#pragma unroll 2
        for (int i = 0; i < DM; i++) {
            const float* xr = xpad + i * PADP;
#pragma unroll
            for (int t = 0; t < 3; t++) {
                const float* wp = wT + (t * DM + i) * DM + obase;
                ull w01, w23, w45, w67;
                ldg2x2(wp, w01, w23);
                ldg2x2(wp + 4, w45, w67);
#pragma unroll
                for (int k = 0; k < 4; k++) {
                    float xv = xr[offs[t][k]];
                    ull xx = pack2(xv, xv);
                    acc[0][k] = fma2(xx, w01, acc[0][k]);
                    acc[1][k] = fma2(xx, w23, acc[1][k]);
                    acc[2][k] = fma2(xx, w45, acc[2][k]);
                    acc[3][k] = fma2(xx, w67, acc[3][k]);
                }
            }
        }
#pragma unroll
        for (int j = 0; j < 4; j++) {
            int o0 = obase + 2 * j;
            float b0 = bias[o0], b1 = bias[o0 + 1];
            float* d0 = dst + o0 * PSTR;
            float* d1 = d0 + PSTR;
#pragma unroll
            for (int k = 0; k < 4; k++) {
                int p = pg * 128 + lane + 32 * k;
                if (p < NPIX) {
                    float2 v = unpack2(acc[j][k]);
                    d0[p] = silu(v.x + b0);
                    d1[p] = silu(v.y + b1);
                }
            }
        }
    }
}

// -------- pointwise 128->128 + silu; ADD=1: dst = dst + silu(pw(src)) --------
// Same o-pair structure as k_dirconv (8 o-channels per warp, 2 pixel groups).
template <int ADD>
__global__ __launch_bounds__(512, 1) void k_pw(const float* __restrict__ srcb,
                                               const float* __restrict__ wT,  // [i][o]
                                               const float* __restrict__ bias,
                                               float* __restrict__ dstb) {
    extern __shared__ float xsm[];  // DM*XST
    int b = blockIdx.x, d = blockIdx.y;
    int tid = threadIdx.x, lane = tid & 31, wid = tid >> 5;
    const float* src = srcb + (size_t)(d * NB + b) * DM * PSTR;
    float*       dst = dstb + (size_t)(d * NB + b) * DM * PSTR;

    for (int c = wid; c < DM; c += 16) {
        const float* s = src + c * PSTR;
        float* xq = xsm + c * XST;
        for (int p = lane; p < NPIX; p += 32) xq[p] = s[p];
        if (lane < 31) xq[NPIX + lane] = 0.f;
    }
    __syncthreads();

    const int obase = wid * 8;

#pragma unroll
    for (int pg = 0; pg < 2; pg++) {
        const int pbase = pg * 128 + lane;
        ull acc[4][4];
#pragma unroll
        for (int j = 0; j < 4; j++)
#pragma unroll
            for (int k = 0; k < 4; k++) acc[j][k] = 0ull;

#pragma unroll 2
        for (int i = 0; i < DM; i++) {
            const float* wp = wT + i * DM + obase;
            ull w01, w23, w45, w67;
            ldg2x2(wp, w01, w23);
            ldg2x2(wp + 4, w45, w67);
            const float* xr = xsm + i * XST + pbase;
#pragma unroll
            for (int k = 0; k < 4; k++) {
                float xv = xr[32 * k];
                ull xx = pack2(xv, xv);
                acc[0][k] = fma2(xx, w01, acc[0][k]);
                acc[1][k] = fma2(xx, w23, acc[1][k]);
                acc[2][k] = fma2(xx, w45, acc[2][k]);
                acc[3][k] = fma2(xx, w67, acc[3][k]);
            }
        }
#pragma unroll
        for (int j = 0; j < 4; j++) {
            int o0 = obase + 2 * j;
            float b0 = bias[o0], b1 = bias[o0 + 1];
            float* d0 = dst + o0 * PSTR;
            float* d1 = d0 + PSTR;
#pragma unroll
            for (int k = 0; k < 4; k++) {
                int p = pbase + 32 * k;
                if (p < NPIX) {
                    float2 v = unpack2(acc[j][k]);
                    float y0 = silu(v.x + b0), y1 = silu(v.y + b1);
                    if (ADD) { y0 += d0[p]; y1 += d1[p]; }
                    d0[p] = y0;
                    d1[p] = y1;
                }
            }
        }
    }
}

// -------- fused: fin(128->64) per dir, tanh-clamp, sum dirs, prelu/4, heads --------
__global__ __launch_bounds__(256, 1) void k_fin(
    const float* __restrict__ xsb, const float* __restrict__ wT,  // [i][o] 128x64
    const float* __restrict__ bias, const float* __restrict__ prelu,
    const float* __restrict__ pdww, const float* __restrict__ pdwb,
    const float* __restrict__ ppw,
    const float* __restrict__ vl1w, const float* __restrict__ vl1b,
    const float* __restrict__ vl2w, const float* __restrict__ vl2b,
    const float* __restrict__ vlfw, const float* __restrict__ vlfb,
    const float* __restrict__ pscale, const float* __restrict__ vscale,
    float* __restrict__ out) {
    extern __shared__ float sm[];
    float* xsm  = sm;              // DM*XST
    float* facc = sm + DM * XST;   // DOUT*PADP
    __shared__ float vbuf[32], h1[32], h2[32];
    int b = blockIdx.x, tid = threadIdx.x, lane = tid & 31, wid = tid >> 5;

    for (int i = tid; i < DOUT * PADP; i += 256) facc[i] = 0.f;

    for (int d = 0; d < 4; d++) {
        __syncthreads();
        const float* src = xsb + (size_t)(d * NB + b) * DM * PSTR;
        for (int c = wid; c < DM; c += 8) {
            const float* s = src + c * PSTR;
            float* xq = xsm + c * XST;
            for (int p = lane; p < NPIX; p += 32) xq[p] = s[p];
            if (lane < 31) xq[NPIX + lane] = 0.f;
        }
        __syncthreads();

        for (int pass = 0; pass < 2; pass++) {
            int obase = pass * 32 + wid * 4;
            ull acc[4][4];
#pragma unroll
            for (int j = 0; j < 4; j++)
#pragma unroll
                for (int k = 0; k < 4; k++) acc[j][k] = 0ull;

#pragma unroll 4
            for (int i = 0; i < DM; i++) {
                float4 wv = *(const float4*)(wT + i * DOUT + obase);
                ull w0 = pack2(wv.x, wv.x), w1 = pack2(wv.y, wv.y);
                ull w2 = pack2(wv.z, wv.z), w3 = pack2(wv.w, wv.w);
                const ull* xr = (const ull*)(xsm + i * XST) + lane;
#pragma unroll
                for (int k = 0; k < 4; k++) {
                    ull xx = xr[32 * k];
                    acc[0][k] = fma2(xx, w0, acc[0][k]);
                    acc[1][k] = fma2(xx, w1, acc[1][k]);
                    acc[2][k] = fma2(xx, w2, acc[2][k]);
                    acc[3][k] = fma2(xx, w3, acc[3][k]);
                }
            }
#pragma unroll
            for (int j = 0; j < 4; j++) {
                int o = obase + j;
                float bv = bias[o];
                float* fo = facc + o * PADP;
#pragma unroll
                for (int k = 0; k < 4; k++) {
                    int px = 2 * (lane + 32 * k);
                    float2 v = unpack2(acc[j][k]);
                    if (px < NPIX) {
                        int h = px / 15, w = px - h * 15;
                        fo[(h + 1) * 17 + w + 1] += MAXF * tanhf((v.x + bv) * INV_MAXF);
                    }
                    if (px + 1 < NPIX) {
                        int h = (px + 1) / 15, w = (px + 1) - h * 15;
                        fo[(h + 1) * 17 + w + 1] += MAXF * tanhf((v.y + bv) * INV_MAXF);
                    }
                }
            }
        }
    }
    __syncthreads();

    // prelu + /4
    for (int idx = tid; idx < DOUT * NPIX; idx += 256) {
        int o = idx / NPIX, p = idx - o * NPIX;
        int h = p / 15, w = p - h * 15;
        float* fp = &facc[o * PADP + (h + 1) * 17 + w + 1];
        float v = *fp;
        *fp = (v >= 0.f ? v : prelu[o] * v) * 0.25f;
    }
    __syncthreads();

    // policy head
    if (tid < NPIX) {
        int h = tid / 15, w = tid - h * 15;
        int base = (h + 1) * 17 + (w + 1);
        float acc = 0.f;
        for (int c = 0; c < DP; c++) {
            const float* fc = facc + c * PADP + base;
            const float* wk = pdww + c * 9;
            float s = pdwb[c];
#pragma unroll
            for (int r = 0; r < 3; r++)
#pragma unroll
                for (int cc = 0; cc < 3; cc++)
                    s += wk[r * 3 + cc] * fc[(r - 1) * 17 + (cc - 1)];
            s = (s >= 0.f) ? s : s * 0.0625f;
            s = fminf(fmaxf(s, -MAXF), MAXF);
            acc += ppw[c] * s;
        }
        acc = (acc >= 0.f) ? acc : acc * 0.0625f;
        out[NB * 3 + (size_t)b * NPIX + tid] = acc * pscale[0];
    }
    __syncthreads();

    // value head (warp 0)
    if (wid == 0) {
        const float* fc = facc + (DP + lane) * PADP;
        float s = 0.f;
        for (int h = 0; h < 15; h++)
#pragma unroll
            for (int w = 0; w < 15; w++) s += fc[(h + 1) * 17 + w + 1];
        vbuf[lane] = fmaxf(s * (1.f / 225.f), 0.f);
        __syncwarp();
        float a = vl1b[lane];
        for (int i = 0; i < 32; i++) a += vl1w[lane * 32 + i] * vbuf[i];
        h1[lane] = fminf(fmaxf(a, 0.f), MAXM);
        __syncwarp();
        float g = vl2b[lane];
        for (int i = 0; i < 32; i++) g += vl2w[lane * 32 + i] * h1[i];
        h2[lane] = fminf(fmaxf(g, 0.f), MAXM);
        __syncwarp();
        if (lane < 3) {
            float o = vlfb[lane];
            for (int i = 0; i < 32; i++) o += vlfw[lane * 32 + i] * h2[i];
            out[(size_t)b * 3 + lane] = o * vscale[0];
        }
    }
}

// ---------------- host ----------------
extern "C" void kernel_launch(void* const* d_in, const int* in_sizes, int n_in,
                              void* d_out, int out_size) {
    const float* x       = (const float*)d_in[0];
    const float* map_w   = (const float*)d_in[1];
    const float* map_b   = (const float*)d_in[2];
    const float* dconv_w = (const float*)d_in[3];
    const float* dconv_b = (const float*)d_in[4];
    const float* c1_w    = (const float*)d_in[5];
    const float* c1_b    = (const float*)d_in[6];
    const float* r0_w1   = (const float*)d_in[7];
    const float* r0_b1   = (const float*)d_in[8];
    const float* r0_w2   = (const float*)d_in[9];
    const float* r0_b2   = (const float*)d_in[10];
    const float* fin_w   = (const float*)d_in[11];
    const float* fin_b   = (const float*)d_in[12];
    const float* prelu_w = (const float*)d_in[13];
    const float* pdw_w   = (const float*)d_in[14];
    const float* pdw_b   = (const float*)d_in[15];
    const float* ppw_w   = (const float*)d_in[16];
    const float* vl1_w   = (const float*)d_in[17];
    const float* vl1_b   = (const float*)d_in[18];
    const float* vl2_w   = (const float*)d_in[19];
    const float* vl2_b   = (const float*)d_in[20];
    const float* vlf_w   = (const float*)d_in[21];
    const float* vlf_b   = (const float*)d_in[22];
    const float* pscale  = (const float*)d_in[23];
    const float* vscale  = (const float*)d_in[24];
    float* out = (float*)d_out;

    float *xs, *tmp, *wdc, *wc1, *wr1, *wr2, *wfn;
    cudaGetSymbolAddress((void**)&xs,  g_xs);
    cudaGetSymbolAddress((void**)&tmp, g_tmp);
    cudaGetSymbolAddress((void**)&wdc, g_wdc);
    cudaGetSymbolAddress((void**)&wc1, g_wc1);
    cudaGetSymbolAddress((void**)&wr1, g_wr1);
    cudaGetSymbolAddress((void**)&wr2, g_wr2);
    cudaGetSymbolAddress((void**)&wfn, g_wfn);

    cudaFuncSetAttribute(k_dirconv, cudaFuncAttributeMaxDynamicSharedMemorySize, SMA);
    cudaFuncSetAttribute(k_pw<0>,   cudaFuncAttributeMaxDynamicSharedMemorySize, SMB);
    cudaFuncSetAttribute(k_pw<1>,   cudaFuncAttributeMaxDynamicSharedMemorySize, SMB);
    cudaFuncSetAttribute(k_fin,     cudaFuncAttributeMaxDynamicSharedMemorySize, SMC);

    // launches 1-2: weight transposes (ncu -s 5 lands on k_dirconv layer 1)
    k_xpose<<<256, 256>>>(dconv_w, wdc, 12, DM, DM);
    k_xpose_rest<<<128, 256>>>(c1_w, r0_w1, r0_w2, fin_w, wc1, wr1, wr2, wfn);

    dim3 gbd(NB, 4);
    k_map<<<gbd, 256>>>(x, map_w, map_b, xs);
    for (int l = 0; l < 4; l++) {
        k_dirconv<<<gbd, 512, SMA>>>(xs, tmp, wdc + l * 3 * DM * DM,
                                     dconv_b + l * DM);
        k_pw<1><<<gbd, 512, SMB>>>(tmp, wc1 + l * DM * DM, c1_b + l * DM, xs);
    }
    k_pw<0><<<gbd, 512, SMB>>>(xs, wr1, r0_b1, tmp);
    k_pw<1><<<gbd, 512, SMB>>>(tmp, wr2, r0_b2, xs);

    k_fin<<<NB, 256, SMC>>>(xs, wfn, fin_b, prelu_w, pdw_w, pdw_b, ppw_w,
                            vl1_w, vl1_b, vl2_w, vl2_b, vlf_w, vlf_b,
                            pscale, vscale, out);
}

// round 7
// speedup vs baseline: 1.4775x; 1.1791x over previous
#include <cuda_runtime.h>
#include <math.h>

typedef unsigned long long ull;

#define NB   512
#define DM   128
#define DOUT 64
#define DP   32
#define NPIX 225
#define PSTR 228          // global per-channel pixel stride (floats)
#define PADP 292          // padded 17x17 (289) channel stride in smem
#define XST  256          // smem dense pixel stride
#define MAXF 31.75f
#define INV_MAXF (1.0f/31.75f)
#define MAXM (127.0f/3.515625f)

#define SMA ((DM*PADP + DM*DM)*4)     // k_dirconv smem: activations + 1-tap weights
#define SMB ((DM*XST  + DM*DM)*4)     // k_pw smem: activations + weights
#define SMC (DM*XST*4 + DOUT*PADP*4)  // k_fin smem

// ---------------- device scratch (no allocation) ----------------
__device__ __align__(16) float g_xs [4ull*NB*DM*PSTR];
__device__ __align__(16) float g_tmp[4ull*NB*DM*PSTR];
__device__ __align__(16) float g_wdc[12*DM*DM];   // dconv  [l*3+t][i][o]
__device__ __align__(16) float g_wc1[4*DM*DM];    // c1     [l][i][o]
__device__ __align__(16) float g_wr1[DM*DM];      // r0_w1  [i][o]
__device__ __align__(16) float g_wr2[DM*DM];      // r0_w2  [i][o]
__device__ __align__(16) float g_wfn[DM*DOUT];    // fin    [i][o]

// tap offsets (dr,dc): tap t reads x[h+dr][w+dc]
__constant__ int c_dr[4][3] = {{0,0,0},{-1,0,1},{-1,0,1},{1,0,-1}};
__constant__ int c_dc[4][3] = {{-1,0,1},{0,0,0},{-1,0,1},{-1,0,1}};

// ---------------- f32x2 helpers ----------------
__device__ __forceinline__ ull pack2(float lo, float hi) {
    ull r; asm("mov.b64 %0, {%1,%2};" : "=l"(r) : "f"(lo), "f"(hi)); return r;
}
__device__ __forceinline__ float2 unpack2(ull v) {
    float2 f; asm("mov.b64 {%0,%1}, %2;" : "=f"(f.x), "=f"(f.y) : "l"(v)); return f;
}
__device__ __forceinline__ ull fma2(ull a, ull b, ull c) {
    ull d; asm("fma.rn.f32x2 %0, %1, %2, %3;" : "=l"(d) : "l"(a), "l"(b), "l"(c)); return d;
}
__device__ __forceinline__ float silu(float x) {
    return __fdividef(x, 1.f + __expf(-x));
}

// ---------------- transpose: dconv [12][o][i] -> [12][i][o] ----------------
__global__ void k_xpose(const float* __restrict__ src, float* __restrict__ dst,
                        int nmat, int R, int C) {
    int n = nmat * R * C;
    for (int idx = blockIdx.x * blockDim.x + threadIdx.x; idx < n;
         idx += gridDim.x * blockDim.x) {
        int m = idx / (R * C);
        int rem = idx - m * R * C;
        int r = rem / C, c = rem - r * C;
        dst[(m * C + c) * R + r] = src[idx];
    }
}

// ---------------- transpose the remaining 4 weight families in ONE launch ----------------
__global__ void k_xpose_rest(const float* __restrict__ c1,
                             const float* __restrict__ r1,
                             const float* __restrict__ r2,
                             const float* __restrict__ fin,
                             float* __restrict__ wc1, float* __restrict__ wr1,
                             float* __restrict__ wr2, float* __restrict__ wfn) {
    const int N1 = 4 * DM * DM;
    const int N2 = N1 + DM * DM;
    const int N3 = N2 + DM * DM;
    const int N4 = N3 + DOUT * DM;
    for (int idx = blockIdx.x * blockDim.x + threadIdx.x; idx < N4;
         idx += gridDim.x * blockDim.x) {
        if (idx < N1) {
            int m = idx / (DM * DM);
            int rem = idx - m * DM * DM;
            int r = rem / DM, c = rem - r * DM;
            wc1[(m * DM + c) * DM + r] = c1[idx];
        } else if (idx < N2) {
            int i2 = idx - N1;
            int r = i2 / DM, c = i2 - r * DM;
            wr1[c * DM + r] = r1[i2];
        } else if (idx < N3) {
            int i2 = idx - N2;
            int r = i2 / DM, c = i2 - r * DM;
            wr2[c * DM + r] = r2[i2];
        } else {
            int i2 = idx - N3;
            int r = i2 / DM, c = i2 - r * DM;  // r = o (64), c = i (128)
            wfn[c * DOUT + r] = fin[i2];
        }
    }
}

// ---------------- input map conv (2 -> 128) + silu ----------------
__global__ __launch_bounds__(256) void k_map(const float* __restrict__ x,
                                             const float* __restrict__ mw,
                                             const float* __restrict__ mb,
                                             float* __restrict__ xsb) {
    int b = blockIdx.x, d = blockIdx.y, tid = threadIdx.x;
    __shared__ float xp[2 * PADP];
    for (int i = tid; i < 2 * PADP; i += 256) xp[i] = 0.f;
    __syncthreads();
    const float* xb = x + (size_t)b * 2 * NPIX;
    for (int i = tid; i < 2 * NPIX; i += 256) {
        int c = i / NPIX, p = i - c * NPIX;
        int h = p / 15, w = p - h * 15;
        xp[c * PADP + (h + 1) * 17 + (w + 1)] = xb[i];
    }
    __syncthreads();
    int dr[3], dc[3];
#pragma unroll
    for (int t = 0; t < 3; t++) { dr[t] = c_dr[d][t]; dc[t] = c_dc[d][t]; }
    float* dst = xsb + (size_t)(d * NB + b) * DM * PSTR;
    for (int idx = tid; idx < DM * NPIX; idx += 256) {
        int o = idx / NPIX, p = idx - o * NPIX;
        int h = p / 15, w = p - h * 15;
        float acc = mb[o];
#pragma unroll
        for (int t = 0; t < 3; t++) {
            int off = (h + 1 + dr[t]) * 17 + (w + 1 + dc[t]);
            acc += mw[(t * DM + o) * 2 + 0] * xp[off]
                 + mw[(t * DM + o) * 2 + 1] * xp[PADP + off];
        }
        dst[o * PSTR + p] = silu(acc);
    }
}

// -------- directional 3-tap conv 128->128 + silu --------
// 512 threads / 16 warps; each warp owns 8 output channels.
// Weights staged in smem per tap (64KB tiles); inner reads are broadcast LDS.128.
__global__ __launch_bounds__(512, 1) void k_dirconv(const float* __restrict__ srcb,
                                                    float* __restrict__ dstb,
                                                    const float* __restrict__ wT, // [3][i][o]
                                                    const float* __restrict__ bias) {
    extern __shared__ float smbuf[];
    float* xpad = smbuf;              // DM*PADP
    float* wsm  = smbuf + DM * PADP;  // DM*DM (one tap)
    int b = blockIdx.x, d = blockIdx.y;
    int tid = threadIdx.x, lane = tid & 31, wid = tid >> 5;
    const float* src = srcb + (size_t)(d * NB + b) * DM * PSTR;
    float*       dst = dstb + (size_t)(d * NB + b) * DM * PSTR;

    for (int i = tid; i < DM * PADP; i += 512) xpad[i] = 0.f;
    __syncthreads();
    for (int c = wid; c < DM; c += 16) {
        const float* s = src + c * PSTR;
        float* xq = xpad + c * PADP;
        for (int p = lane; p < NPIX; p += 32) {
            int h = p / 15, w = p - h * 15;
            xq[(h + 1) * 17 + (w + 1)] = s[p];
        }
    }

    const int obase = wid * 8;    // warp's 8 output channels

#pragma unroll
    for (int pg = 0; pg < 2; pg++) {
        int offs[3][4];
#pragma unroll
        for (int k = 0; k < 4; k++) {
            int p = pg * 128 + lane + 32 * k;
            int pv = (p < NPIX) ? p : 0;
            int h = pv / 15, w = pv - h * 15;
#pragma unroll
            for (int t = 0; t < 3; t++)
                offs[t][k] = (h + 1 + c_dr[d][t]) * 17 + (w + 1 + c_dc[d][t]);
        }

        ull acc[4][4];
#pragma unroll
        for (int j = 0; j < 4; j++)
#pragma unroll
            for (int k = 0; k < 4; k++) acc[j][k] = 0ull;

        for (int t = 0; t < 3; t++) {
            __syncthreads();   // protect wsm from readers of the previous tap
            {
                const float4* ws = (const float4*)(wT + t * DM * DM);
                float4* wd = (float4*)wsm;
#pragma unroll
                for (int j = 0; j < 8; j++) wd[tid + 512 * j] = ws[tid + 512 * j];
            }
            __syncthreads();

#pragma unroll 2
            for (int i = 0; i < DM; i++) {
                const float* xr = xpad + i * PADP;
                ulonglong2 wa = *(const ulonglong2*)(wsm + i * DM + obase);
                ulonglong2 wb = *(const ulonglong2*)(wsm + i * DM + obase + 4);
#pragma unroll
                for (int k = 0; k < 4; k++) {
                    float xv = xr[offs[t][k]];
                    ull xx = pack2(xv, xv);
                    acc[0][k] = fma2(xx, wa.x, acc[0][k]);
                    acc[1][k] = fma2(xx, wa.y, acc[1][k]);
                    acc[2][k] = fma2(xx, wb.x, acc[2][k]);
                    acc[3][k] = fma2(xx, wb.y, acc[3][k]);
                }
            }
        }
#pragma unroll
        for (int j = 0; j < 4; j++) {
            int o0 = obase + 2 * j;
            float b0 = bias[o0], b1 = bias[o0 + 1];
            float* d0 = dst + o0 * PSTR;
            float* d1 = d0 + PSTR;
#pragma unroll
            for (int k = 0; k < 4; k++) {
                int p = pg * 128 + lane + 32 * k;
                if (p < NPIX) {
                    float2 v = unpack2(acc[j][k]);
                    d0[p] = silu(v.x + b0);
                    d1[p] = silu(v.y + b1);
                }
            }
        }
    }
}

// -------- pointwise 128->128 + silu; ADD=1: dst = dst + silu(pw(src)) --------
// Weights staged once in smem (no extra syncs); broadcast LDS.128 in the inner loop.
template <int ADD>
__global__ __launch_bounds__(512, 1) void k_pw(const float* __restrict__ srcb,
                                               const float* __restrict__ wT,  // [i][o]
                                               const float* __restrict__ bias,
                                               float* __restrict__ dstb) {
    extern __shared__ float smbuf[];
    float* xsm = smbuf;              // DM*XST
    float* wsm = smbuf + DM * XST;   // DM*DM
    int b = blockIdx.x, d = blockIdx.y;
    int tid = threadIdx.x, lane = tid & 31, wid = tid >> 5;
    const float* src = srcb + (size_t)(d * NB + b) * DM * PSTR;
    float*       dst = dstb + (size_t)(d * NB + b) * DM * PSTR;

    for (int c = wid; c < DM; c += 16) {
        const float* s = src + c * PSTR;
        float* xq = xsm + c * XST;
        for (int p = lane; p < NPIX; p += 32) xq[p] = s[p];
        if (lane < 31) xq[NPIX + lane] = 0.f;
    }
    {
        const float4* ws = (const float4*)wT;
        float4* wd = (float4*)wsm;
#pragma unroll
        for (int j = 0; j < 8; j++) wd[tid + 512 * j] = ws[tid + 512 * j];
    }
    __syncthreads();

    const int obase = wid * 8;

#pragma unroll
    for (int pg = 0; pg < 2; pg++) {
        const int pbase = pg * 128 + lane;
        ull acc[4][4];
#pragma unroll
        for (int j = 0; j < 4; j++)
#pragma unroll
            for (int k = 0; k < 4; k++) acc[j][k] = 0ull;

#pragma unroll 4
        for (int i = 0; i < DM; i++) {
            ulonglong2 wa = *(const ulonglong2*)(wsm + i * DM + obase);
            ulonglong2 wb = *(const ulonglong2*)(wsm + i * DM + obase + 4);
            const float* xr = xsm + i * XST + pbase;
#pragma unroll
            for (int k = 0; k < 4; k++) {
                float xv = xr[32 * k];
                ull xx = pack2(xv, xv);
                acc[0][k] = fma2(xx, wa.x, acc[0][k]);
                acc[1][k] = fma2(xx, wa.y, acc[1][k]);
                acc[2][k] = fma2(xx, wb.x, acc[2][k]);
                acc[3][k] = fma2(xx, wb.y, acc[3][k]);
            }
        }
#pragma unroll
        for (int j = 0; j < 4; j++) {
            int o0 = obase + 2 * j;
            float b0 = bias[o0], b1 = bias[o0 + 1];
            float* d0 = dst + o0 * PSTR;
            float* d1 = d0 + PSTR;
#pragma unroll
            for (int k = 0; k < 4; k++) {
                int p = pbase + 32 * k;
                if (p < NPIX) {
                    float2 v = unpack2(acc[j][k]);
                    float y0 = silu(v.x + b0), y1 = silu(v.y + b1);
                    if (ADD) { y0 += d0[p]; y1 += d1[p]; }
                    d0[p] = y0;
                    d1[p] = y1;
                }
            }
        }
    }
}

// -------- fused: fin(128->64) per dir, tanh-clamp, sum dirs, prelu/4, heads --------
__global__ __launch_bounds__(256, 1) void k_fin(
    const float* __restrict__ xsb, const float* __restrict__ wT,  // [i][o] 128x64
    const float* __restrict__ bias, const float* __restrict__ prelu,
    const float* __restrict__ pdww, const float* __restrict__ pdwb,
    const float* __restrict__ ppw,
    const float* __restrict__ vl1w, const float* __restrict__ vl1b,
    const float* __restrict__ vl2w, const float* __restrict__ vl2b,
    const float* __restrict__ vlfw, const float* __restrict__ vlfb,
    const float* __restrict__ pscale, const float* __restrict__ vscale,
    float* __restrict__ out) {
    extern __shared__ float sm[];
    float* xsm  = sm;              // DM*XST
    float* facc = sm + DM * XST;   // DOUT*PADP
    __shared__ float vbuf[32], h1[32], h2[32];
    int b = blockIdx.x, tid = threadIdx.x, lane = tid & 31, wid = tid >> 5;

    for (int i = tid; i < DOUT * PADP; i += 256) facc[i] = 0.f;

    for (int d = 0; d < 4; d++) {
        __syncthreads();
        const float* src = xsb + (size_t)(d * NB + b) * DM * PSTR;
        for (int c = wid; c < DM; c += 8) {
            const float* s = src + c * PSTR;
            float* xq = xsm + c * XST;
            for (int p = lane; p < NPIX; p += 32) xq[p] = s[p];
            if (lane < 31) xq[NPIX + lane] = 0.f;
        }
        __syncthreads();

        for (int pass = 0; pass < 2; pass++) {
            int obase = pass * 32 + wid * 4;
            ull acc[4][4];
#pragma unroll
            for (int j = 0; j < 4; j++)
#pragma unroll
                for (int k = 0; k < 4; k++) acc[j][k] = 0ull;

#pragma unroll 4
            for (int i = 0; i < DM; i++) {
                float4 wv = *(const float4*)(wT + i * DOUT + obase);
                ull w0 = pack2(wv.x, wv.x), w1 = pack2(wv.y, wv.y);
                ull w2 = pack2(wv.z, wv.z), w3 = pack2(wv.w, wv.w);
                const ull* xr = (const ull*)(xsm + i * XST) + lane;
#pragma unroll
                for (int k = 0; k < 4; k++) {
                    ull xx = xr[32 * k];
                    acc[0][k] = fma2(xx, w0, acc[0][k]);
                    acc[1][k] = fma2(xx, w1, acc[1][k]);
                    acc[2][k] = fma2(xx, w2, acc[2][k]);
                    acc[3][k] = fma2(xx, w3, acc[3][k]);
                }
            }
#pragma unroll
            for (int j = 0; j < 4; j++) {
                int o = obase + j;
                float bv = bias[o];
                float* fo = facc + o * PADP;
#pragma unroll
                for (int k = 0; k < 4; k++) {
                    int px = 2 * (lane + 32 * k);
                    float2 v = unpack2(acc[j][k]);
                    if (px < NPIX) {
                        int h = px / 15, w = px - h * 15;
                        fo[(h + 1) * 17 + w + 1] += MAXF * tanhf((v.x + bv) * INV_MAXF);
                    }
                    if (px + 1 < NPIX) {
                        int h = (px + 1) / 15, w = (px + 1) - h * 15;
                        fo[(h + 1) * 17 + w + 1] += MAXF * tanhf((v.y + bv) * INV_MAXF);
                    }
                }
            }
        }
    }
    __syncthreads();

    // prelu + /4
    for (int idx = tid; idx < DOUT * NPIX; idx += 256) {
        int o = idx / NPIX, p = idx - o * NPIX;
        int h = p / 15, w = p - h * 15;
        float* fp = &facc[o * PADP + (h + 1) * 17 + w + 1];
        float v = *fp;
        *fp = (v >= 0.f ? v : prelu[o] * v) * 0.25f;
    }
    __syncthreads();

    // policy head
    if (tid < NPIX) {
        int h = tid / 15, w = tid - h * 15;
        int base = (h + 1) * 17 + (w + 1);
        float acc = 0.f;
        for (int c = 0; c < DP; c++) {
            const float* fc = facc + c * PADP + base;
            const float* wk = pdww + c * 9;
            float s = pdwb[c];
#pragma unroll
            for (int r = 0; r < 3; r++)
#pragma unroll
                for (int cc = 0; cc < 3; cc++)
                    s += wk[r * 3 + cc] * fc[(r - 1) * 17 + (cc - 1)];
            s = (s >= 0.f) ? s : s * 0.0625f;
            s = fminf(fmaxf(s, -MAXF), MAXF);
            acc += ppw[c] * s;
        }
        acc = (acc >= 0.f) ? acc : acc * 0.0625f;
        out[NB * 3 + (size_t)b * NPIX + tid] = acc * pscale[0];
    }
    __syncthreads();

    // value head (warp 0)
    if (wid == 0) {
        const float* fc = facc + (DP + lane) * PADP;
        float s = 0.f;
        for (int h = 0; h < 15; h++)
#pragma unroll
            for (int w = 0; w < 15; w++) s += fc[(h + 1) * 17 + w + 1];
        vbuf[lane] = fmaxf(s * (1.f / 225.f), 0.f);
        __syncwarp();
        float a = vl1b[lane];
        for (int i = 0; i < 32; i++) a += vl1w[lane * 32 + i] * vbuf[i];
        h1[lane] = fminf(fmaxf(a, 0.f), MAXM);
        __syncwarp();
        float g = vl2b[lane];
        for (int i = 0; i < 32; i++) g += vl2w[lane * 32 + i] * h1[i];
        h2[lane] = fminf(fmaxf(g, 0.f), MAXM);
        __syncwarp();
        if (lane < 3) {
            float o = vlfb[lane];
            for (int i = 0; i < 32; i++) o += vlfw[lane * 32 + i] * h2[i];
            out[(size_t)b * 3 + lane] = o * vscale[0];
        }
    }
}

// ---------------- host ----------------
extern "C" void kernel_launch(void* const* d_in, const int* in_sizes, int n_in,
                              void* d_out, int out_size) {
    const float* x       = (const float*)d_in[0];
    const float* map_w   = (const float*)d_in[1];
    const float* map_b   = (const float*)d_in[2];
    const float* dconv_w = (const float*)d_in[3];
    const float* dconv_b = (const float*)d_in[4];
    const float* c1_w    = (const float*)d_in[5];
    const float* c1_b    = (const float*)d_in[6];
    const float* r0_w1   = (const float*)d_in[7];
    const float* r0_b1   = (const float*)d_in[8];
    const float* r0_w2   = (const float*)d_in[9];
    const float* r0_b2   = (const float*)d_in[10];
    const float* fin_w   = (const float*)d_in[11];
    const float* fin_b   = (const float*)d_in[12];
    const float* prelu_w = (const float*)d_in[13];
    const float* pdw_w   = (const float*)d_in[14];
    const float* pdw_b   = (const float*)d_in[15];
    const float* ppw_w   = (const float*)d_in[16];
    const float* vl1_w   = (const float*)d_in[17];
    const float* vl1_b   = (const float*)d_in[18];
    const float* vl2_w   = (const float*)d_in[19];
    const float* vl2_b   = (const float*)d_in[20];
    const float* vlf_w   = (const float*)d_in[21];
    const float* vlf_b   = (const float*)d_in[22];
    const float* pscale  = (const float*)d_in[23];
    const float* vscale  = (const float*)d_in[24];
    float* out = (float*)d_out;

    float *xs, *tmp, *wdc, *wc1, *wr1, *wr2, *wfn;
    cudaGetSymbolAddress((void**)&xs,  g_xs);
    cudaGetSymbolAddress((void**)&tmp, g_tmp);
    cudaGetSymbolAddress((void**)&wdc, g_wdc);
    cudaGetSymbolAddress((void**)&wc1, g_wc1);
    cudaGetSymbolAddress((void**)&wr1, g_wr1);
    cudaGetSymbolAddress((void**)&wr2, g_wr2);
    cudaGetSymbolAddress((void**)&wfn, g_wfn);

    cudaFuncSetAttribute(k_dirconv, cudaFuncAttributeMaxDynamicSharedMemorySize, SMA);
    cudaFuncSetAttribute(k_pw<0>,   cudaFuncAttributeMaxDynamicSharedMemorySize, SMB);
    cudaFuncSetAttribute(k_pw<1>,   cudaFuncAttributeMaxDynamicSharedMemorySize, SMB);
    cudaFuncSetAttribute(k_fin,     cudaFuncAttributeMaxDynamicSharedMemorySize, SMC);

    // launches 1-2: weight transposes (ncu -s 5 lands on k_dirconv layer 1)
    k_xpose<<<256, 256>>>(dconv_w, wdc, 12, DM, DM);
    k_xpose_rest<<<128, 256>>>(c1_w, r0_w1, r0_w2, fin_w, wc1, wr1, wr2, wfn);

    dim3 gbd(NB, 4);
    k_map<<<gbd, 256>>>(x, map_w, map_b, xs);
    for (int l = 0; l < 4; l++) {
        k_dirconv<<<gbd, 512, SMA>>>(xs, tmp, wdc + l * 3 * DM * DM,
                                     dconv_b + l * DM);
        k_pw<1><<<gbd, 512, SMB>>>(tmp, wc1 + l * DM * DM, c1_b + l * DM, xs);
    }
    k_pw<0><<<gbd, 512, SMB>>>(xs, wr1, r0_b1, tmp);
    k_pw<1><<<gbd, 512, SMB>>>(tmp, wr2, r0_b2, xs);

    k_fin<<<NB, 256, SMC>>>(xs, wfn, fin_b, prelu_w, pdw_w, pdw_b, ppw_w,
                            vl1_w, vl1_b, vl2_w, vl2_b, vlf_w, vlf_b,
                            pscale, vscale, out);
}

// round 8
// speedup vs baseline: 1.5893x; 1.0756x over previous
#include <cuda_runtime.h>
#include <math.h>

typedef unsigned long long ull;

#define NB   512
#define DM   128
#define DOUT 64
#define DP   32
#define NPIX 225
#define PSTR 228          // global per-channel pixel stride (floats)
#define PADP 292          // padded 17x17 (289) channel stride in smem
#define XST  256          // smem dense pixel stride
#define MAXF 31.75f
#define INV_MAXF (1.0f/31.75f)
#define MAXM (127.0f/3.515625f)

#define SMA ((DM*PADP + DM*DM)*4)     // k_dirconv smem: activations + 1-tap weights
#define SMB ((DM*XST  + DM*DM)*4)     // k_pw smem: activations + weights
#define SMC (DM*XST*4 + DOUT*PADP*4)  // k_fin smem

// ---------------- device scratch (no allocation) ----------------
__device__ __align__(16) float g_xs [4ull*NB*DM*PSTR];
__device__ __align__(16) float g_tmp[4ull*NB*DM*PSTR];
__device__ __align__(16) float g_wdc[12*DM*DM];   // dconv  [l*3+t][i][o]
__device__ __align__(16) float g_wc1[4*DM*DM];    // c1     [l][i][o]
__device__ __align__(16) float g_wr1[DM*DM];      // r0_w1  [i][o]
__device__ __align__(16) float g_wr2[DM*DM];      // r0_w2  [i][o]
__device__ __align__(16) float g_wfn[DM*DOUT];    // fin    [i][o]

// tap offsets (dr,dc): tap t reads x[h+dr][w+dc]
__constant__ int c_dr[4][3] = {{0,0,0},{-1,0,1},{-1,0,1},{1,0,-1}};
__constant__ int c_dc[4][3] = {{-1,0,1},{0,0,0},{-1,0,1},{-1,0,1}};

// ---------------- f32x2 helpers ----------------
__device__ __forceinline__ ull pack2(float lo, float hi) {
    ull r; asm("mov.b64 %0, {%1,%2};" : "=l"(r) : "f"(lo), "f"(hi)); return r;
}
__device__ __forceinline__ float2 unpack2(ull v) {
    float2 f; asm("mov.b64 {%0,%1}, %2;" : "=f"(f.x), "=f"(f.y) : "l"(v)); return f;
}
__device__ __forceinline__ ull fma2(ull a, ull b, ull c) {
    ull d; asm("fma.rn.f32x2 %0, %1, %2, %3;" : "=l"(d) : "l"(a), "l"(b), "l"(c)); return d;
}
__device__ __forceinline__ float silu(float x) {
    return __fdividef(x, 1.f + __expf(-x));
}

// ---------------- transpose: dconv [12][o][i] -> [12][i][o] ----------------
__global__ void k_xpose(const float* __restrict__ src, float* __restrict__ dst,
                        int nmat, int R, int C) {
    int n = nmat * R * C;
    for (int idx = blockIdx.x * blockDim.x + threadIdx.x; idx < n;
         idx += gridDim.x * blockDim.x) {
        int m = idx / (R * C);
        int rem = idx - m * R * C;
        int r = rem / C, c = rem - r * C;
        dst[(m * C + c) * R + r] = src[idx];
    }
}

// ---------------- transpose the remaining 4 weight families in ONE launch ----------------
__global__ void k_xpose_rest(const float* __restrict__ c1,
                             const float* __restrict__ r1,
                             const float* __restrict__ r2,
                             const float* __restrict__ fin,
                             float* __restrict__ wc1, float* __restrict__ wr1,
                             float* __restrict__ wr2, float* __restrict__ wfn) {
    const int N1 = 4 * DM * DM;
    const int N2 = N1 + DM * DM;
    const int N3 = N2 + DM * DM;
    const int N4 = N3 + DOUT * DM;
    for (int idx = blockIdx.x * blockDim.x + threadIdx.x; idx < N4;
         idx += gridDim.x * blockDim.x) {
        if (idx < N1) {
            int m = idx / (DM * DM);
            int rem = idx - m * DM * DM;
            int r = rem / DM, c = rem - r * DM;
            wc1[(m * DM + c) * DM + r] = c1[idx];
        } else if (idx < N2) {
            int i2 = idx - N1;
            int r = i2 / DM, c = i2 - r * DM;
            wr1[c * DM + r] = r1[i2];
        } else if (idx < N3) {
            int i2 = idx - N2;
            int r = i2 / DM, c = i2 - r * DM;
            wr2[c * DM + r] = r2[i2];
        } else {
            int i2 = idx - N3;
            int r = i2 / DM, c = i2 - r * DM;  // r = o (64), c = i (128)
            wfn[c * DOUT + r] = fin[i2];
        }
    }
}

// ---------------- input map conv (2 -> 128) + silu ----------------
__global__ __launch_bounds__(256) void k_map(const float* __restrict__ x,
                                             const float* __restrict__ mw,
                                             const float* __restrict__ mb,
                                             float* __restrict__ xsb) {
    int b = blockIdx.x, d = blockIdx.y, tid = threadIdx.x;
    __shared__ float xp[2 * PADP];
    for (int i = tid; i < 2 * PADP; i += 256) xp[i] = 0.f;
    __syncthreads();
    const float* xb = x + (size_t)b * 2 * NPIX;
    for (int i = tid; i < 2 * NPIX; i += 256) {
        int c = i / NPIX, p = i - c * NPIX;
        int h = p / 15, w = p - h * 15;
        xp[c * PADP + (h + 1) * 17 + (w + 1)] = xb[i];
    }
    __syncthreads();
    int dr[3], dc[3];
#pragma unroll
    for (int t = 0; t < 3; t++) { dr[t] = c_dr[d][t]; dc[t] = c_dc[d][t]; }
    float* dst = xsb + (size_t)(d * NB + b) * DM * PSTR;
    for (int idx = tid; idx < DM * NPIX; idx += 256) {
        int o = idx / NPIX, p = idx - o * NPIX;
        int h = p / 15, w = p - h * 15;
        float acc = mb[o];
#pragma unroll
        for (int t = 0; t < 3; t++) {
            int off = (h + 1 + dr[t]) * 17 + (w + 1 + dc[t]);
            acc += mw[(t * DM + o) * 2 + 0] * xp[off]
                 + mw[(t * DM + o) * 2 + 1] * xp[PADP + off];
        }
        dst[o * PSTR + p] = silu(acc);
    }
}

// -------- directional 3-tap conv 128->128 + silu --------
// 512 threads / 16 warps. Warp = (pixel-group, o-group): 8 o-groups of 16
// channels x 2 pixel-groups of 128 px. Per (i,t): 4 uniform LDS.128 (w) +
// 4 scalar LDS (x) = 8 wavefronts for 32 FMA2 -> 4:1, FMA/L1 balanced.
__global__ __launch_bounds__(512, 1) void k_dirconv(const float* __restrict__ srcb,
                                                    float* __restrict__ dstb,
                                                    const float* __restrict__ wT, // [3][i][o]
                                                    const float* __restrict__ bias) {
    extern __shared__ float smbuf[];
    float* xpad = smbuf;              // DM*PADP
    float* wsm  = smbuf + DM * PADP;  // DM*DM (one tap)
    int b = blockIdx.x, d = blockIdx.y;
    int tid = threadIdx.x, lane = tid & 31, wid = tid >> 5;
    const float* src = srcb + (size_t)(d * NB + b) * DM * PSTR;
    float*       dst = dstb + (size_t)(d * NB + b) * DM * PSTR;

    for (int i = tid; i < DM * PADP; i += 512) xpad[i] = 0.f;
    __syncthreads();
    for (int c = wid; c < DM; c += 16) {
        const float* s = src + c * PSTR;
        float* xq = xpad + c * PADP;
        for (int p = lane; p < NPIX; p += 32) {
            int h = p / 15, w = p - h * 15;
            xq[(h + 1) * 17 + (w + 1)] = s[p];
        }
    }

    const int pg    = wid >> 3;         // pixel group 0/1
    const int obase = (wid & 7) * 16;   // warp's 16 output channels

    int offs[3][4];
#pragma unroll
    for (int k = 0; k < 4; k++) {
        int p = pg * 128 + lane + 32 * k;
        int pv = (p < NPIX) ? p : 0;
        int h = pv / 15, w = pv - h * 15;
#pragma unroll
        for (int t = 0; t < 3; t++)
            offs[t][k] = (h + 1 + c_dr[d][t]) * 17 + (w + 1 + c_dc[d][t]);
    }

    ull acc[8][4];
#pragma unroll
    for (int j = 0; j < 8; j++)
#pragma unroll
        for (int k = 0; k < 4; k++) acc[j][k] = 0ull;

    for (int t = 0; t < 3; t++) {
        __syncthreads();   // protect wsm from readers of the previous tap
        {
            const float4* ws = (const float4*)(wT + t * DM * DM);
            float4* wd = (float4*)wsm;
#pragma unroll
            for (int j = 0; j < 8; j++) wd[tid + 512 * j] = ws[tid + 512 * j];
        }
        __syncthreads();

        for (int i = 0; i < DM; i++) {
            const float* xr = xpad + i * PADP;
            const float* wrow = wsm + i * DM + obase;
            ulonglong2 wa = *(const ulonglong2*)(wrow);
            ulonglong2 wb = *(const ulonglong2*)(wrow + 4);
            ulonglong2 wc = *(const ulonglong2*)(wrow + 8);
            ulonglong2 we = *(const ulonglong2*)(wrow + 12);
#pragma unroll
            for (int k = 0; k < 4; k++) {
                float xv = xr[offs[t][k]];
                ull xx = pack2(xv, xv);
                acc[0][k] = fma2(xx, wa.x, acc[0][k]);
                acc[1][k] = fma2(xx, wa.y, acc[1][k]);
                acc[2][k] = fma2(xx, wb.x, acc[2][k]);
                acc[3][k] = fma2(xx, wb.y, acc[3][k]);
                acc[4][k] = fma2(xx, wc.x, acc[4][k]);
                acc[5][k] = fma2(xx, wc.y, acc[5][k]);
                acc[6][k] = fma2(xx, we.x, acc[6][k]);
                acc[7][k] = fma2(xx, we.y, acc[7][k]);
            }
        }
    }
#pragma unroll
    for (int j = 0; j < 8; j++) {
        int o0 = obase + 2 * j;
        float b0 = bias[o0], b1 = bias[o0 + 1];
        float* d0 = dst + o0 * PSTR;
        float* d1 = d0 + PSTR;
#pragma unroll
        for (int k = 0; k < 4; k++) {
            int p = pg * 128 + lane + 32 * k;
            if (p < NPIX) {
                float2 v = unpack2(acc[j][k]);
                d0[p] = silu(v.x + b0);
                d1[p] = silu(v.y + b1);
            }
        }
    }
}

// -------- pointwise 128->128 + silu; ADD=1: dst = dst + silu(pw(src)) --------
// Same 16-o-per-warp structure; weights staged once.
template <int ADD>
__global__ __launch_bounds__(512, 1) void k_pw(const float* __restrict__ srcb,
                                               const float* __restrict__ wT,  // [i][o]
                                               const float* __restrict__ bias,
                                               float* __restrict__ dstb) {
    extern __shared__ float smbuf[];
    float* xsm = smbuf;              // DM*XST
    float* wsm = smbuf + DM * XST;   // DM*DM
    int b = blockIdx.x, d = blockIdx.y;
    int tid = threadIdx.x, lane = tid & 31, wid = tid >> 5;
    const float* src = srcb + (size_t)(d * NB + b) * DM * PSTR;
    float*       dst = dstb + (size_t)(d * NB + b) * DM * PSTR;

    for (int c = wid; c < DM; c += 16) {
        const float* s = src + c * PSTR;
        float* xq = xsm + c * XST;
        for (int p = lane; p < NPIX; p += 32) xq[p] = s[p];
        if (lane < 31) xq[NPIX + lane] = 0.f;
    }
    {
        const float4* ws = (const float4*)wT;
        float4* wd = (float4*)wsm;
#pragma unroll
        for (int j = 0; j < 8; j++) wd[tid + 512 * j] = ws[tid + 512 * j];
    }
    __syncthreads();

    const int pg    = wid >> 3;
    const int obase = (wid & 7) * 16;
    const int pbase = pg * 128 + lane;

    ull acc[8][4];
#pragma unroll
    for (int j = 0; j < 8; j++)
#pragma unroll
        for (int k = 0; k < 4; k++) acc[j][k] = 0ull;

    for (int i = 0; i < DM; i++) {
        const float* wrow = wsm + i * DM + obase;
        ulonglong2 wa = *(const ulonglong2*)(wrow);
        ulonglong2 wb = *(const ulonglong2*)(wrow + 4);
        ulonglong2 wc = *(const ulonglong2*)(wrow + 8);
        ulonglong2 we = *(const ulonglong2*)(wrow + 12);
        const float* xr = xsm + i * XST + pbase;
#pragma unroll
        for (int k = 0; k < 4; k++) {
            float xv = xr[32 * k];
            ull xx = pack2(xv, xv);
            acc[0][k] = fma2(xx, wa.x, acc[0][k]);
            acc[1][k] = fma2(xx, wa.y, acc[1][k]);
            acc[2][k] = fma2(xx, wb.x, acc[2][k]);
            acc[3][k] = fma2(xx, wb.y, acc[3][k]);
            acc[4][k] = fma2(xx, wc.x, acc[4][k]);
            acc[5][k] = fma2(xx, wc.y, acc[5][k]);
            acc[6][k] = fma2(xx, we.x, acc[6][k]);
            acc[7][k] = fma2(xx, we.y, acc[7][k]);
        }
    }
#pragma unroll
    for (int j = 0; j < 8; j++) {
        int o0 = obase + 2 * j;
        float b0 = bias[o0], b1 = bias[o0 + 1];
        float* d0 = dst + o0 * PSTR;
        float* d1 = d0 + PSTR;
#pragma unroll
        for (int k = 0; k < 4; k++) {
            int p = pbase + 32 * k;
            if (p < NPIX) {
                float2 v = unpack2(acc[j][k]);
                float y0 = silu(v.x + b0), y1 = silu(v.y + b1);
                if (ADD) { y0 += d0[p]; y1 += d1[p]; }
                d0[p] = y0;
                d1[p] = y1;
            }
        }
    }
}

// -------- fused: fin(128->64) per dir, tanh-clamp, sum dirs, prelu/4, heads --------
__global__ __launch_bounds__(256, 1) void k_fin(
    const float* __restrict__ xsb, const float* __restrict__ wT,  // [i][o] 128x64
    const float* __restrict__ bias, const float* __restrict__ prelu,
    const float* __restrict__ pdww, const float* __restrict__ pdwb,
    const float* __restrict__ ppw,
    const float* __restrict__ vl1w, const float* __restrict__ vl1b,
    const float* __restrict__ vl2w, const float* __restrict__ vl2b,
    const float* __restrict__ vlfw, const float* __restrict__ vlfb,
    const float* __restrict__ pscale, const float* __restrict__ vscale,
    float* __restrict__ out) {
    extern __shared__ float sm[];
    float* xsm  = sm;              // DM*XST
    float* facc = sm + DM * XST;   // DOUT*PADP
    __shared__ float vbuf[32], h1[32], h2[32];
    int b = blockIdx.x, tid = threadIdx.x, lane = tid & 31, wid = tid >> 5;

    for (int i = tid; i < DOUT * PADP; i += 256) facc[i] = 0.f;

    for (int d = 0; d < 4; d++) {
        __syncthreads();
        const float* src = xsb + (size_t)(d * NB + b) * DM * PSTR;
        for (int c = wid; c < DM; c += 8) {
            const float* s = src + c * PSTR;
            float* xq = xsm + c * XST;
            for (int p = lane; p < NPIX; p += 32) xq[p] = s[p];
            if (lane < 31) xq[NPIX + lane] = 0.f;
        }
        __syncthreads();

        for (int pass = 0; pass < 2; pass++) {
            int obase = pass * 32 + wid * 4;
            ull acc[4][4];
#pragma unroll
            for (int j = 0; j < 4; j++)
#pragma unroll
                for (int k = 0; k < 4; k++) acc[j][k] = 0ull;

#pragma unroll 4
            for (int i = 0; i < DM; i++) {
                float4 wv = *(const float4*)(wT + i * DOUT + obase);
                ull w0 = pack2(wv.x, wv.x), w1 = pack2(wv.y, wv.y);
                ull w2 = pack2(wv.z, wv.z), w3 = pack2(wv.w, wv.w);
                const ull* xr = (const ull*)(xsm + i * XST) + lane;
#pragma unroll
                for (int k = 0; k < 4; k++) {
                    ull xx = xr[32 * k];
                    acc[0][k] = fma2(xx, w0, acc[0][k]);
                    acc[1][k] = fma2(xx, w1, acc[1][k]);
                    acc[2][k] = fma2(xx, w2, acc[2][k]);
                    acc[3][k] = fma2(xx, w3, acc[3][k]);
                }
            }
#pragma unroll
            for (int j = 0; j < 4; j++) {
                int o = obase + j;
                float bv = bias[o];
                float* fo = facc + o * PADP;
#pragma unroll
                for (int k = 0; k < 4; k++) {
                    int px = 2 * (lane + 32 * k);
                    float2 v = unpack2(acc[j][k]);
                    if (px < NPIX) {
                        int h = px / 15, w = px - h * 15;
                        fo[(h + 1) * 17 + w + 1] += MAXF * tanhf((v.x + bv) * INV_MAXF);
                    }
                    if (px + 1 < NPIX) {
                        int h = (px + 1) / 15, w = (px + 1) - h * 15;
                        fo[(h + 1) * 17 + w + 1] += MAXF * tanhf((v.y + bv) * INV_MAXF);
                    }
                }
            }
        }
    }
    __syncthreads();

    // prelu + /4
    for (int idx = tid; idx < DOUT * NPIX; idx += 256) {
        int o = idx / NPIX, p = idx - o * NPIX;
        int h = p / 15, w = p - h * 15;
        float* fp = &facc[o * PADP + (h + 1) * 17 + w + 1];
        float v = *fp;
        *fp = (v >= 0.f ? v : prelu[o] * v) * 0.25f;
    }
    __syncthreads();

    // policy head
    if (tid < NPIX) {
        int h = tid / 15, w = tid - h * 15;
        int base = (h + 1) * 17 + (w + 1);
        float acc = 0.f;
        for (int c = 0; c < DP; c++) {
            const float* fc = facc + c * PADP + base;
            const float* wk = pdww + c * 9;
            float s = pdwb[c];
#pragma unroll
            for (int r = 0; r < 3; r++)
#pragma unroll
                for (int cc = 0; cc < 3; cc++)
                    s += wk[r * 3 + cc] * fc[(r - 1) * 17 + (cc - 1)];
            s = (s >= 0.f) ? s : s * 0.0625f;
            s = fminf(fmaxf(s, -MAXF), MAXF);
            acc += ppw[c] * s;
        }
        acc = (acc >= 0.f) ? acc : acc * 0.0625f;
        out[NB * 3 + (size_t)b * NPIX + tid] = acc * pscale[0];
    }
    __syncthreads();

    // value head (warp 0)
    if (wid == 0) {
        const float* fc = facc + (DP + lane) * PADP;
        float s = 0.f;
        for (int h = 0; h < 15; h++)
#pragma unroll
            for (int w = 0; w < 15; w++) s += fc[(h + 1) * 17 + w + 1];
        vbuf[lane] = fmaxf(s * (1.f / 225.f), 0.f);
        __syncwarp();
        float a = vl1b[lane];
        for (int i = 0; i < 32; i++) a += vl1w[lane * 32 + i] * vbuf[i];
        h1[lane] = fminf(fmaxf(a, 0.f), MAXM);
        __syncwarp();
        float g = vl2b[lane];
        for (int i = 0; i < 32; i++) g += vl2w[lane * 32 + i] * h1[i];
        h2[lane] = fminf(fmaxf(g, 0.f), MAXM);
        __syncwarp();
        if (lane < 3) {
            float o = vlfb[lane];
            for (int i = 0; i < 32; i++) o += vlfw[lane * 32 + i] * h2[i];
            out[(size_t)b * 3 + lane] = o * vscale[0];
        }
    }
}

// ---------------- host ----------------
extern "C" void kernel_launch(void* const* d_in, const int* in_sizes, int n_in,
                              void* d_out, int out_size) {
    const float* x       = (const float*)d_in[0];
    const float* map_w   = (const float*)d_in[1];
    const float* map_b   = (const float*)d_in[2];
    const float* dconv_w = (const float*)d_in[3];
    const float* dconv_b = (const float*)d_in[4];
    const float* c1_w    = (const float*)d_in[5];
    const float* c1_b    = (const float*)d_in[6];
    const float* r0_w1   = (const float*)d_in[7];
    const float* r0_b1   = (const float*)d_in[8];
    const float* r0_w2   = (const float*)d_in[9];
    const float* r0_b2   = (const float*)d_in[10];
    const float* fin_w   = (const float*)d_in[11];
    const float* fin_b   = (const float*)d_in[12];
    const float* prelu_w = (const float*)d_in[13];
    const float* pdw_w   = (const float*)d_in[14];
    const float* pdw_b   = (const float*)d_in[15];
    const float* ppw_w   = (const float*)d_in[16];
    const float* vl1_w   = (const float*)d_in[17];
    const float* vl1_b   = (const float*)d_in[18];
    const float* vl2_w   = (const float*)d_in[19];
    const float* vl2_b   = (const float*)d_in[20];
    const float* vlf_w   = (const float*)d_in[21];
    const float* vlf_b   = (const float*)d_in[22];
    const float* pscale  = (const float*)d_in[23];
    const float* vscale  = (const float*)d_in[24];
    float* out = (float*)d_out;

    float *xs, *tmp, *wdc, *wc1, *wr1, *wr2, *wfn;
    cudaGetSymbolAddress((void**)&xs,  g_xs);
    cudaGetSymbolAddress((void**)&tmp, g_tmp);
    cudaGetSymbolAddress((void**)&wdc, g_wdc);
    cudaGetSymbolAddress((void**)&wc1, g_wc1);
    cudaGetSymbolAddress((void**)&wr1, g_wr1);
    cudaGetSymbolAddress((void**)&wr2, g_wr2);
    cudaGetSymbolAddress((void**)&wfn, g_wfn);

    cudaFuncSetAttribute(k_dirconv, cudaFuncAttributeMaxDynamicSharedMemorySize, SMA);
    cudaFuncSetAttribute(k_pw<0>,   cudaFuncAttributeMaxDynamicSharedMemorySize, SMB);
    cudaFuncSetAttribute(k_pw<1>,   cudaFuncAttributeMaxDynamicSharedMemorySize, SMB);
    cudaFuncSetAttribute(k_fin,     cudaFuncAttributeMaxDynamicSharedMemorySize, SMC);

    // launches 1-2: weight transposes (ncu -s 5 lands on k_dirconv layer 1)
    k_xpose<<<256, 256>>>(dconv_w, wdc, 12, DM, DM);
    k_xpose_rest<<<128, 256>>>(c1_w, r0_w1, r0_w2, fin_w, wc1, wr1, wr2, wfn);

    dim3 gbd(NB, 4);
    k_map<<<gbd, 256>>>(x, map_w, map_b, xs);
    for (int l = 0; l < 4; l++) {
        k_dirconv<<<gbd, 512, SMA>>>(xs, tmp, wdc + l * 3 * DM * DM,
                                     dconv_b + l * DM);
        k_pw<1><<<gbd, 512, SMB>>>(tmp, wc1 + l * DM * DM, c1_b + l * DM, xs);
    }
    k_pw<0><<<gbd, 512, SMB>>>(xs, wr1, r0_b1, tmp);
    k_pw<1><<<gbd, 512, SMB>>>(tmp, wr2, r0_b2, xs);

    k_fin<<<NB, 256, SMC>>>(xs, wfn, fin_b, prelu_w, pdw_w, pdw_b, ppw_w,
                            vl1_w, vl1_b, vl2_w, vl2_b, vlf_w, vlf_b,
                            pscale, vscale, out);
}